// round 4
// baseline (speedup 1.0000x reference)
#include <cuda_runtime.h>
#include <cuda_bf16.h>
#include <math_constants.h>

// Problem constants
#define NN   50000
#define EE   600000
#define DD   128
#define GG   64
#define NCLS 10

// ---------------- device scratch ----------------
__device__ float g_h   [NN * DD];   // layer input/output features
__device__ float g_q   [NN * DD];
__device__ float g_k   [NN * DD];
__device__ float g_v   [NN * DD];
__device__ float g_sk  [NN * DD];   // skip (x@Ws + bs)

__device__ int   g_deg [NN];
__device__ int   g_cur [NN];
__device__ int   g_rowptr[NN + 1];
__device__ int   g_col [EE];        // src node per CSR-sorted edge (grouped by dst)
__device__ int   g_aux [256];

__device__ float g_pool[GG * DD];
__device__ int   g_cnt [GG];

// ---------------- init ----------------
__global__ void init_kernel() {
    int i = blockIdx.x * blockDim.x + threadIdx.x;
    if (i < NN) { g_deg[i] = 0; g_cur[i] = 0; }
    if (i < GG * DD) g_pool[i] = 0.0f;
    if (i < GG) g_cnt[i] = 0;
}

// ---------------- CSR build ----------------
__global__ void hist_kernel(const int* __restrict__ dst) {
    int e = blockIdx.x * blockDim.x + threadIdx.x;
    if (e < EE) atomicAdd(&g_deg[dst[e]], 1);
}
__global__ void scanA_kernel() {
    __shared__ int s[512];
    int t = threadIdx.x;
    int idx = blockIdx.x * 512 + t;
    int val = (idx < NN) ? g_deg[idx] : 0;
    s[t] = val;
    __syncthreads();
    for (int off = 1; off < 512; off <<= 1) {
        int x = (t >= off) ? s[t - off] : 0;
        __syncthreads();
        s[t] += x;
        __syncthreads();
    }
    if (idx < NN) g_rowptr[idx] = s[t];
    if (t == 511) g_aux[blockIdx.x] = s[511];
}
__global__ void scanB_kernel(int nblocks) {
    if (threadIdx.x == 0 && blockIdx.x == 0) {
        int run = 0;
        for (int i = 0; i < nblocks; i++) { int v = g_aux[i]; g_aux[i] = run; run += v; }
    }
}
__global__ void scanC_kernel() {
    int t = threadIdx.x;
    int idx = blockIdx.x * 512 + t;
    if (idx < NN) g_rowptr[idx] = g_rowptr[idx] - g_deg[idx] + g_aux[blockIdx.x];
    if (idx == 0) g_rowptr[NN] = EE;
}
__global__ void scatter_kernel(const int* __restrict__ src, const int* __restrict__ dst) {
    int e = blockIdx.x * blockDim.x + threadIdx.x;
    if (e < EE) {
        int d = dst[e];
        int pos = g_rowptr[d] + atomicAdd(&g_cur[d], 1);
        g_col[pos] = src[e];
    }
}

// ---------------- fused 4-way GEMM:  out = A(N x 128) @ W(128 x 128) + b ----------------
// NOTE: A is selected INSIDE device code when useGh != 0 (never pass __device__
// symbols as kernel args from host — on GB300/ATS that silently reads the host
// shadow copy).
__global__ __launch_bounds__(256) void gemm4_kernel(
    const float* __restrict__ Ain, int useGh,
    const float* __restrict__ Wq, const float* __restrict__ Wk,
    const float* __restrict__ Wv, const float* __restrict__ Ws,
    const float* __restrict__ bq, const float* __restrict__ bk,
    const float* __restrict__ bv, const float* __restrict__ bs)
{
    const float* A = useGh ? (const float*)g_h : Ain;

    const int which = blockIdx.y;
    const float* W    = (which == 0) ? Wq : (which == 1) ? Wk : (which == 2) ? Wv : Ws;
    const float* bias = (which == 0) ? bq : (which == 1) ? bk : (which == 2) ? bv : bs;
    float* O          = (which == 0) ? g_q : (which == 1) ? g_k : (which == 2) ? g_v : g_sk;

    __shared__ float As[16][128];   // [k][row]
    __shared__ float Bs[16][128];   // [k][col]

    const int tid  = threadIdx.x;
    const int row0 = blockIdx.x * 128;
    const int tr   = (tid >> 4) * 8;
    const int tc   = (tid & 15) * 8;

    float acc[8][8];
    #pragma unroll
    for (int i = 0; i < 8; i++)
        #pragma unroll
        for (int j = 0; j < 8; j++) acc[i][j] = 0.0f;

    for (int k0 = 0; k0 < 128; k0 += 16) {
        #pragma unroll
        for (int it = 0; it < 2; it++) {
            int f  = tid + it * 256;
            int r  = f >> 2;
            int c4 = (f & 3) * 4;
            int gr = row0 + r;
            float4 a = make_float4(0.f, 0.f, 0.f, 0.f);
            if (gr < NN) a = *(const float4*)(A + (size_t)gr * 128 + k0 + c4);
            As[c4 + 0][r] = a.x; As[c4 + 1][r] = a.y;
            As[c4 + 2][r] = a.z; As[c4 + 3][r] = a.w;
        }
        #pragma unroll
        for (int it = 0; it < 2; it++) {
            int f  = tid + it * 256;
            int r  = f >> 5;
            int c4 = (f & 31) * 4;
            *(float4*)(&Bs[r][c4]) = *(const float4*)(W + (size_t)(k0 + r) * 128 + c4);
        }
        __syncthreads();

        #pragma unroll
        for (int kk = 0; kk < 16; kk++) {
            float a[8], b[8];
            float4 a0 = *(const float4*)(&As[kk][tr]);
            float4 a1 = *(const float4*)(&As[kk][tr + 4]);
            float4 b0 = *(const float4*)(&Bs[kk][tc]);
            float4 b1 = *(const float4*)(&Bs[kk][tc + 4]);
            a[0]=a0.x; a[1]=a0.y; a[2]=a0.z; a[3]=a0.w;
            a[4]=a1.x; a[5]=a1.y; a[6]=a1.z; a[7]=a1.w;
            b[0]=b0.x; b[1]=b0.y; b[2]=b0.z; b[3]=b0.w;
            b[4]=b1.x; b[5]=b1.y; b[6]=b1.z; b[7]=b1.w;
            #pragma unroll
            for (int i = 0; i < 8; i++)
                #pragma unroll
                for (int j = 0; j < 8; j++)
                    acc[i][j] = fmaf(a[i], b[j], acc[i][j]);
        }
        __syncthreads();
    }

    float bb[8];
    #pragma unroll
    for (int j = 0; j < 8; j++) bb[j] = bias[tc + j];

    #pragma unroll
    for (int i = 0; i < 8; i++) {
        int gr = row0 + tr + i;
        if (gr < NN) {
            float4 o0 = make_float4(acc[i][0] + bb[0], acc[i][1] + bb[1],
                                    acc[i][2] + bb[2], acc[i][3] + bb[3]);
            float4 o1 = make_float4(acc[i][4] + bb[4], acc[i][5] + bb[5],
                                    acc[i][6] + bb[6], acc[i][7] + bb[7]);
            *(float4*)(&O[(size_t)gr * 128 + tc])     = o0;
            *(float4*)(&O[(size_t)gr * 128 + tc + 4]) = o1;
        }
    }
}

// ---------------- attention: one warp per dst node, online softmax ----------------
__global__ __launch_bounds__(256) void attn_kernel() {
    int node = (blockIdx.x * blockDim.x + threadIdx.x) >> 5;
    if (node >= NN) return;
    int lane = threadIdx.x & 31;
    const int base = node * 128 + lane * 4;

    float4 q4 = *(const float4*)(&g_q[base]);
    int beg = g_rowptr[node];
    int end = g_rowptr[node + 1];

    float m = -CUDART_INF_F, den = 0.f;
    float a0 = 0.f, a1 = 0.f, a2 = 0.f, a3 = 0.f;

    for (int i = beg; i < end; i++) {
        int s = g_col[i];
        float4 k4 = *(const float4*)(&g_k[(size_t)s * 128 + lane * 4]);
        float4 v4 = *(const float4*)(&g_v[(size_t)s * 128 + lane * 4]);
        float p = q4.x * k4.x + q4.y * k4.y + q4.z * k4.z + q4.w * k4.w;
        p += __shfl_xor_sync(0xffffffffu, p, 16);
        p += __shfl_xor_sync(0xffffffffu, p, 8);
        p += __shfl_xor_sync(0xffffffffu, p, 4);
        p += __shfl_xor_sync(0xffffffffu, p, 2);
        p += __shfl_xor_sync(0xffffffffu, p, 1);
        float score = p * 0.08838834764831845f;  // 1/sqrt(128)
        float nm = fmaxf(m, score);
        float sc = __expf(m - nm);               // 0 when m == -inf
        float w  = __expf(score - nm);
        den = den * sc + w;
        a0 = fmaf(a0, sc, w * v4.x);
        a1 = fmaf(a1, sc, w * v4.y);
        a2 = fmaf(a2, sc, w * v4.z);
        a3 = fmaf(a3, sc, w * v4.w);
        m = nm;
    }

    float inv = (den > 0.f) ? (1.0f / den) : 0.0f;
    float4 sk4 = *(const float4*)(&g_sk[base]);
    float4 o;
    o.x = fmaxf(fmaf(a0, inv, sk4.x), 0.f);
    o.y = fmaxf(fmaf(a1, inv, sk4.y), 0.f);
    o.z = fmaxf(fmaf(a2, inv, sk4.z), 0.f);
    o.w = fmaxf(fmaf(a3, inv, sk4.w), 0.f);
    *(float4*)(&g_h[base]) = o;
}

// ---------------- pooling ----------------
__global__ void count_kernel(const int* __restrict__ batch) {
    int n = blockIdx.x * blockDim.x + threadIdx.x;
    if (n < NN) atomicAdd(&g_cnt[batch[n]], 1);
}
__global__ __launch_bounds__(128) void pool_kernel(const int* __restrict__ batch) {
    int t = threadIdx.x;                   // channel
    int n0 = blockIdx.x * 256;
    int nend = min(n0 + 256, NN);
    int gcur = -1;
    float acc = 0.f;
    for (int n = n0; n < nend; n++) {
        int g = batch[n];
        if (g != gcur) {
            if (gcur >= 0) atomicAdd(&g_pool[gcur * 128 + t], acc);
            gcur = g; acc = 0.f;
        }
        acc += g_h[(size_t)n * 128 + t];
    }
    if (gcur >= 0) atomicAdd(&g_pool[gcur * 128 + t], acc);
}

// ---------------- head: mean, FC, log_softmax ----------------
__global__ __launch_bounds__(640) void head_kernel(
    const float* __restrict__ Wfc, const float* __restrict__ bfc, float* __restrict__ out)
{
    __shared__ float logits[GG][NCLS];
    __shared__ float rmax[GG], rlse[GG];
    int t = threadIdx.x;
    int g = t / NCLS, c = t % NCLS;

    float cnt = (float)g_cnt[g];
    if (cnt < 1.f) cnt = 1.f;
    float s = 0.f;
    for (int d = 0; d < 128; d++)
        s += g_pool[g * 128 + d] * Wfc[d * NCLS + c];
    s = s / cnt + bfc[c];
    logits[g][c] = s;
    __syncthreads();

    if (t < GG) {
        float m = -CUDART_INF_F;
        for (int j = 0; j < NCLS; j++) m = fmaxf(m, logits[t][j]);
        float l = 0.f;
        for (int j = 0; j < NCLS; j++) l += expf(logits[t][j] - m);
        rmax[t] = m;
        rlse[t] = logf(l);
    }
    __syncthreads();
    out[g * NCLS + c] = logits[g][c] - rmax[g] - rlse[g];
}

// ---------------- launch ----------------
extern "C" void kernel_launch(void* const* d_in, const int* in_sizes, int n_in,
                              void* d_out, int out_size)
{
    const float* x   = (const float*)d_in[0];
    const int* eidx  = (const int*)d_in[1];
    const int* batch = (const int*)d_in[2];
    const float* Wq  = (const float*)d_in[3];
    const float* bq  = (const float*)d_in[4];
    const float* Wk  = (const float*)d_in[5];
    const float* bk  = (const float*)d_in[6];
    const float* Wv  = (const float*)d_in[7];
    const float* bv  = (const float*)d_in[8];
    const float* Ws  = (const float*)d_in[9];
    const float* bs  = (const float*)d_in[10];
    const float* Wfc = (const float*)d_in[11];
    const float* bfc = (const float*)d_in[12];
    float* out = (float*)d_out;

    const int* src = eidx;        // row 0
    const int* dst = eidx + EE;   // row 1

    const int scanBlocks = (NN + 511) / 512;   // 98

    init_kernel<<<(NN + 255) / 256, 256>>>();
    hist_kernel<<<(EE + 255) / 256, 256>>>(dst);
    scanA_kernel<<<scanBlocks, 512>>>();
    scanB_kernel<<<1, 32>>>(scanBlocks);
    scanC_kernel<<<scanBlocks, 512>>>();
    scatter_kernel<<<(EE + 255) / 256, 256>>>(src, dst);

    const int gemmGridX = (NN + 127) / 128;    // 391
    dim3 gemmGrid(gemmGridX, 4);
    const int nodeWarpBlocks = (NN * 32 + 255) / 256;   // 6250
    const int nodeBlocks     = (NN + 255) / 256;

    // ----- layer 0 (input = x) -----
    gemm4_kernel<<<gemmGrid, 256>>>(x, 0, Wq, Wk, Wv, Ws, bq, bk, bv, bs);
    attn_kernel<<<nodeWarpBlocks, 256>>>();

    // ----- layer 1 (input = g_h, selected in DEVICE code via useGh=1) -----
    gemm4_kernel<<<gemmGrid, 256>>>(nullptr, 1,
        Wq + 128 * 128, Wk + 128 * 128, Wv + 128 * 128, Ws + 128 * 128,
        bq + 128, bk + 128, bv + 128, bs + 128);
    attn_kernel<<<nodeWarpBlocks, 256>>>();

    // ----- pooling + head -----
    count_kernel<<<nodeBlocks, 256>>>(batch);
    pool_kernel<<<nodeBlocks, 128>>>(batch);
    head_kernel<<<1, 640>>>(Wfc, bfc, out);
}

// round 9
// speedup vs baseline: 1.2291x; 1.2291x over previous
#include <cuda_runtime.h>
#include <cuda_bf16.h>
#include <math_constants.h>
#include <cstdint>

// Problem constants
#define NN   50000
#define EE   600000
#define DD   128
#define GG   64
#define NCLS 10

// ---------------- device scratch ----------------
__device__ float g_h   [NN * DD];
__device__ float g_q   [NN * DD];
__device__ float g_k   [NN * DD];
__device__ float g_v   [NN * DD];
__device__ float g_sk  [NN * DD];

__device__ int   g_deg [NN];
__device__ int   g_cur [NN];
__device__ int   g_rowptr[NN + 1];
__device__ int   g_col [EE];
__device__ int   g_aux [256];

__device__ float g_pool[GG * DD];
__device__ int   g_cnt [GG];

// ---------------- init ----------------
__global__ void init_kernel() {
    int i = blockIdx.x * blockDim.x + threadIdx.x;
    if (i < NN) { g_deg[i] = 0; g_cur[i] = 0; }
    if (i < GG * DD) g_pool[i] = 0.0f;
    if (i < GG) g_cnt[i] = 0;
}

// ---------------- CSR build ----------------
__global__ void hist_kernel(const int* __restrict__ dst) {
    int e = blockIdx.x * blockDim.x + threadIdx.x;
    if (e < EE) atomicAdd(&g_deg[dst[e]], 1);
}
__global__ void scanA_kernel() {
    __shared__ int s[512];
    int t = threadIdx.x;
    int idx = blockIdx.x * 512 + t;
    int val = (idx < NN) ? g_deg[idx] : 0;
    s[t] = val;
    __syncthreads();
    for (int off = 1; off < 512; off <<= 1) {
        int x = (t >= off) ? s[t - off] : 0;
        __syncthreads();
        s[t] += x;
        __syncthreads();
    }
    if (idx < NN) g_rowptr[idx] = s[t];
    if (t == 511) g_aux[blockIdx.x] = s[511];
}
__global__ void scanB_kernel(int nblocks) {   // parallel 1-block exclusive scan
    __shared__ int s[128];
    int t = threadIdx.x;
    int v = (t < nblocks) ? g_aux[t] : 0;
    s[t] = v;
    __syncthreads();
    for (int off = 1; off < 128; off <<= 1) {
        int x = (t >= off) ? s[t - off] : 0;
        __syncthreads();
        s[t] += x;
        __syncthreads();
    }
    if (t < nblocks) g_aux[t] = s[t] - v;
}
__global__ void scanC_kernel() {
    int t = threadIdx.x;
    int idx = blockIdx.x * 512 + t;
    if (idx < NN) g_rowptr[idx] = g_rowptr[idx] - g_deg[idx] + g_aux[blockIdx.x];
    if (idx == 0) g_rowptr[NN] = EE;
}
__global__ void scatter_kernel(const int* __restrict__ src, const int* __restrict__ dst) {
    int e = blockIdx.x * blockDim.x + threadIdx.x;
    if (e < EE) {
        int d = dst[e];
        int pos = g_rowptr[d] + atomicAdd(&g_cur[d], 1);
        g_col[pos] = src[e];
    }
}

// ---------------- HMMA GEMM (mma.sync bf16, fp32 accum, hi/lo split) ----------------
// SMEM layout (bytes); bf16 tiles use 136-element row stride.
static constexpr int STRD   = 136;                  // bf16 elements per row
static constexpr int TILE_B = 128 * STRD * 2;       // 34816
static constexpr int SM_AH   = 0;
static constexpr int SM_AL   = SM_AH + TILE_B;
static constexpr int SM_BH   = SM_AL + TILE_B;      // [k][n] layout
static constexpr int SM_BL   = SM_BH + TILE_B;
static constexpr int SM_BIAS = SM_BL + TILE_B;      // 139264
static constexpr int SM_TOT  = SM_BIAS + 512;       // 139776

__device__ __forceinline__ void split2(float x, __nv_bfloat16& h, __nv_bfloat16& l) {
    h = __float2bfloat16_rn(x);
    l = __float2bfloat16_rn(x - __bfloat162float(h));
}
__device__ __forceinline__ uint32_t pack4(float a, float b) {
    __nv_bfloat16 ha, la, hb, lb;   // unused halves optimized away by caller pattern
    (void)la; (void)lb; (void)ha; (void)hb;
    return 0u;
}

#define MMA_BF16(d, a0, a1, a2, a3, b0, b1) \
    asm volatile( \
        "mma.sync.aligned.m16n8k16.row.col.f32.bf16.bf16.f32 " \
        "{%0,%1,%2,%3}, {%4,%5,%6,%7}, {%8,%9}, {%0,%1,%2,%3};" \
        : "+f"((d)[0]), "+f"((d)[1]), "+f"((d)[2]), "+f"((d)[3]) \
        : "r"(a0), "r"(a1), "r"(a2), "r"(a3), "r"(b0), "r"(b1))

#define LDMATRIX_X2_T(r0, r1, addr) \
    asm volatile("ldmatrix.sync.aligned.m8n8.x2.trans.shared.b16 {%0,%1}, [%2];" \
                 : "=r"(r0), "=r"(r1) : "r"(addr))

__device__ __forceinline__ uint32_t smem_u32(const void* p) {
    uint32_t a;
    asm("{ .reg .u64 t; cvta.to.shared.u64 t, %1; cvt.u32.u64 %0, t; }" : "=r"(a) : "l"(p));
    return a;
}

__global__ __launch_bounds__(256) void gemm_mma_kernel(
    const float* __restrict__ Ain, int useGh,
    const float* __restrict__ Wq, const float* __restrict__ Wk,
    const float* __restrict__ Wv, const float* __restrict__ Ws,
    const float* __restrict__ bq, const float* __restrict__ bk,
    const float* __restrict__ bv, const float* __restrict__ bs)
{
    extern __shared__ char smem[];
    const float* A = useGh ? (const float*)g_h : Ain;
    const uint32_t sb = smem_u32(smem);
    const int tid  = threadIdx.x;
    const int wid  = tid >> 5;
    const int lane = tid & 31;
    const int grp  = lane >> 2;      // 0..7
    const int qid  = lane & 3;       // 0..3
    const int row0 = blockIdx.x * 128;
    float* bias_s = (float*)(smem + SM_BIAS);

    // ---- A tile: fp32 -> bf16 hi/lo, row-major [m][k], stride 136 ----
    for (int it = 0; it < 16; it++) {
        int idx = it * 256 + tid;
        int r  = idx >> 5;
        int k4 = (idx & 31) * 4;
        float4 a = make_float4(0.f, 0.f, 0.f, 0.f);
        int gr = row0 + r;
        if (gr < NN) a = *(const float4*)(A + (size_t)gr * 128 + k4);
        __nv_bfloat16 h0, h1, h2, h3, l0, l1, l2, l3;
        split2(a.x, h0, l0); split2(a.y, h1, l1);
        split2(a.z, h2, l2); split2(a.w, h3, l3);
        uint32_t off = (uint32_t)(r * STRD + k4) * 2;
        uint2 ph = make_uint2(((uint32_t)__bfloat16_as_ushort(h1) << 16) | __bfloat16_as_ushort(h0),
                              ((uint32_t)__bfloat16_as_ushort(h3) << 16) | __bfloat16_as_ushort(h2));
        uint2 pl = make_uint2(((uint32_t)__bfloat16_as_ushort(l1) << 16) | __bfloat16_as_ushort(l0),
                              ((uint32_t)__bfloat16_as_ushort(l3) << 16) | __bfloat16_as_ushort(l2));
        *(uint2*)(smem + SM_AH + off) = ph;
        *(uint2*)(smem + SM_AL + off) = pl;
    }

    const int m0 = wid * 16;

    for (int which = 0; which < 4; which++) {
        const float* W    = (which == 0) ? Wq : (which == 1) ? Wk : (which == 2) ? Wv : Ws;
        const float* bias = (which == 0) ? bq : (which == 1) ? bk : (which == 2) ? bv : bs;
        float* O          = (which == 0) ? g_q : (which == 1) ? g_k : (which == 2) ? g_v : g_sk;

        __syncthreads();   // prior-iteration mma reads of Bs complete
        // ---- B tile: W[k][n] fp32 -> bf16 hi/lo, [k][n] layout, stride 136 ----
        for (int it = 0; it < 16; it++) {
            int idx = it * 256 + tid;
            int k  = idx >> 5;
            int n4 = (idx & 31) * 4;
            float4 w = *(const float4*)(W + (size_t)k * 128 + n4);
            __nv_bfloat16 h0, h1, h2, h3, l0, l1, l2, l3;
            split2(w.x, h0, l0); split2(w.y, h1, l1);
            split2(w.z, h2, l2); split2(w.w, h3, l3);
            uint32_t off = (uint32_t)(k * STRD + n4) * 2;
            uint2 ph = make_uint2(((uint32_t)__bfloat16_as_ushort(h1) << 16) | __bfloat16_as_ushort(h0),
                                  ((uint32_t)__bfloat16_as_ushort(h3) << 16) | __bfloat16_as_ushort(h2));
            uint2 pl = make_uint2(((uint32_t)__bfloat16_as_ushort(l1) << 16) | __bfloat16_as_ushort(l0),
                                  ((uint32_t)__bfloat16_as_ushort(l3) << 16) | __bfloat16_as_ushort(l2));
            *(uint2*)(smem + SM_BH + off) = ph;
            *(uint2*)(smem + SM_BL + off) = pl;
        }
        if (tid < 128) bias_s[tid] = bias[tid];
        __syncthreads();

        // ---- mma mainloop: warp computes rows [m0, m0+16) x all 128 cols ----
        float acc[16][4];
        #pragma unroll
        for (int nt = 0; nt < 16; nt++)
            #pragma unroll
            for (int j = 0; j < 4; j++) acc[nt][j] = 0.f;

        const int rl = lane & 15;   // ldmatrix row-provider index
        #pragma unroll 1
        for (int k0 = 0; k0 < 8; k0++) {
            const int k = k0 * 16;
            // A fragments (manual, conflict-free)
            uint32_t aoff0 = (uint32_t)((m0 + grp) * STRD + k + qid * 2) * 2;
            uint32_t aoff1 = aoff0 + 8u * STRD * 2u;
            uint32_t ah0 = *(const uint32_t*)(smem + SM_AH + aoff0);
            uint32_t ah1 = *(const uint32_t*)(smem + SM_AH + aoff1);
            uint32_t ah2 = *(const uint32_t*)(smem + SM_AH + aoff0 + 16);
            uint32_t ah3 = *(const uint32_t*)(smem + SM_AH + aoff1 + 16);
            uint32_t al0 = *(const uint32_t*)(smem + SM_AL + aoff0);
            uint32_t al1 = *(const uint32_t*)(smem + SM_AL + aoff1);
            uint32_t al2 = *(const uint32_t*)(smem + SM_AL + aoff0 + 16);
            uint32_t al3 = *(const uint32_t*)(smem + SM_AL + aoff1 + 16);

            uint32_t browH = sb + SM_BH + (uint32_t)((k + rl) * STRD) * 2;
            uint32_t browL = sb + SM_BL + (uint32_t)((k + rl) * STRD) * 2;

            #pragma unroll
            for (int nt = 0; nt < 16; nt++) {
                uint32_t bh0, bh1, bl0, bl1;
                LDMATRIX_X2_T(bh0, bh1, browH + nt * 16);   // n0 = nt*8 -> 16 bytes
                LDMATRIX_X2_T(bl0, bl1, browL + nt * 16);
                MMA_BF16(acc[nt], ah0, ah1, ah2, ah3, bh0, bh1);
                MMA_BF16(acc[nt], ah0, ah1, ah2, ah3, bl0, bl1);
                MMA_BF16(acc[nt], al0, al1, al2, al3, bh0, bh1);
            }
        }

        // ---- epilogue: add bias, store fp32 ----
        int r0 = row0 + m0 + grp;
        int r1 = r0 + 8;
        #pragma unroll
        for (int nt = 0; nt < 16; nt++) {
            int c = nt * 8 + qid * 2;
            float b0 = bias_s[c], b1 = bias_s[c + 1];
            if (r0 < NN) {
                float2 o = make_float2(acc[nt][0] + b0, acc[nt][1] + b1);
                *(float2*)(O + (size_t)r0 * 128 + c) = o;
            }
            if (r1 < NN) {
                float2 o = make_float2(acc[nt][2] + b0, acc[nt][3] + b1);
                *(float2*)(O + (size_t)r1 * 128 + c) = o;
            }
        }
    }
}

// ---------------- attention: one warp per dst node, online softmax ----------------
__global__ __launch_bounds__(256) void attn_kernel() {
    int node = (blockIdx.x * blockDim.x + threadIdx.x) >> 5;
    if (node >= NN) return;
    int lane = threadIdx.x & 31;
    const int base = node * 128 + lane * 4;

    float4 q4 = *(const float4*)(&g_q[base]);
    int beg = g_rowptr[node];
    int end = g_rowptr[node + 1];

    float m = -CUDART_INF_F, den = 0.f;
    float a0 = 0.f, a1 = 0.f, a2 = 0.f, a3 = 0.f;

    for (int i = beg; i < end; i++) {
        int s = g_col[i];
        float4 k4 = *(const float4*)(&g_k[(size_t)s * 128 + lane * 4]);
        float4 v4 = *(const float4*)(&g_v[(size_t)s * 128 + lane * 4]);
        float p = q4.x * k4.x + q4.y * k4.y + q4.z * k4.z + q4.w * k4.w;
        p += __shfl_xor_sync(0xffffffffu, p, 16);
        p += __shfl_xor_sync(0xffffffffu, p, 8);
        p += __shfl_xor_sync(0xffffffffu, p, 4);
        p += __shfl_xor_sync(0xffffffffu, p, 2);
        p += __shfl_xor_sync(0xffffffffu, p, 1);
        float score = p * 0.08838834764831845f;  // 1/sqrt(128)
        float nm = fmaxf(m, score);
        float sc = __expf(m - nm);
        float w  = __expf(score - nm);
        den = den * sc + w;
        a0 = fmaf(a0, sc, w * v4.x);
        a1 = fmaf(a1, sc, w * v4.y);
        a2 = fmaf(a2, sc, w * v4.z);
        a3 = fmaf(a3, sc, w * v4.w);
        m = nm;
    }

    float inv = (den > 0.f) ? (1.0f / den) : 0.0f;
    float4 sk4 = *(const float4*)(&g_sk[base]);
    float4 o;
    o.x = fmaxf(fmaf(a0, inv, sk4.x), 0.f);
    o.y = fmaxf(fmaf(a1, inv, sk4.y), 0.f);
    o.z = fmaxf(fmaf(a2, inv, sk4.z), 0.f);
    o.w = fmaxf(fmaf(a3, inv, sk4.w), 0.f);
    *(float4*)(&g_h[base]) = o;
}

// ---------------- pooling ----------------
__global__ void count_kernel(const int* __restrict__ batch) {
    int n = blockIdx.x * blockDim.x + threadIdx.x;
    if (n < NN) atomicAdd(&g_cnt[batch[n]], 1);
}
__global__ __launch_bounds__(128) void pool_kernel(const int* __restrict__ batch) {
    int t = threadIdx.x;
    int n0 = blockIdx.x * 256;
    int nend = min(n0 + 256, NN);
    int gcur = -1;
    float acc = 0.f;
    for (int n = n0; n < nend; n++) {
        int g = batch[n];
        if (g != gcur) {
            if (gcur >= 0) atomicAdd(&g_pool[gcur * 128 + t], acc);
            gcur = g; acc = 0.f;
        }
        acc += g_h[(size_t)n * 128 + t];
    }
    if (gcur >= 0) atomicAdd(&g_pool[gcur * 128 + t], acc);
}

// ---------------- head ----------------
__global__ __launch_bounds__(640) void head_kernel(
    const float* __restrict__ Wfc, const float* __restrict__ bfc, float* __restrict__ out)
{
    __shared__ float logits[GG][NCLS];
    __shared__ float rmax[GG], rlse[GG];
    int t = threadIdx.x;
    int g = t / NCLS, c = t % NCLS;

    float cnt = (float)g_cnt[g];
    if (cnt < 1.f) cnt = 1.f;
    float s = 0.f;
    for (int d = 0; d < 128; d++)
        s += g_pool[g * 128 + d] * Wfc[d * NCLS + c];
    s = s / cnt + bfc[c];
    logits[g][c] = s;
    __syncthreads();

    if (t < GG) {
        float m = -CUDART_INF_F;
        for (int j = 0; j < NCLS; j++) m = fmaxf(m, logits[t][j]);
        float l = 0.f;
        for (int j = 0; j < NCLS; j++) l += expf(logits[t][j] - m);
        rmax[t] = m;
        rlse[t] = logf(l);
    }
    __syncthreads();
    out[g * NCLS + c] = logits[g][c] - rmax[g] - rlse[g];
}

// ---------------- launch ----------------
extern "C" void kernel_launch(void* const* d_in, const int* in_sizes, int n_in,
                              void* d_out, int out_size)
{
    const float* x   = (const float*)d_in[0];
    const int* eidx  = (const int*)d_in[1];
    const int* batch = (const int*)d_in[2];
    const float* Wq  = (const float*)d_in[3];
    const float* bq  = (const float*)d_in[4];
    const float* Wk  = (const float*)d_in[5];
    const float* bk  = (const float*)d_in[6];
    const float* Wv  = (const float*)d_in[7];
    const float* bv  = (const float*)d_in[8];
    const float* Ws  = (const float*)d_in[9];
    const float* bs  = (const float*)d_in[10];
    const float* Wfc = (const float*)d_in[11];
    const float* bfc = (const float*)d_in[12];
    float* out = (float*)d_out;

    const int* src = eidx;        // row 0
    const int* dst = eidx + EE;   // row 1

    cudaFuncSetAttribute(gemm_mma_kernel,
                         cudaFuncAttributeMaxDynamicSharedMemorySize, SM_TOT);

    const int scanBlocks = (NN + 511) / 512;   // 98

    init_kernel<<<(NN + 255) / 256, 256>>>();
    hist_kernel<<<(EE + 255) / 256, 256>>>(dst);
    scanA_kernel<<<scanBlocks, 512>>>();
    scanB_kernel<<<1, 128>>>(scanBlocks);
    scanC_kernel<<<scanBlocks, 512>>>();
    scatter_kernel<<<(EE + 255) / 256, 256>>>(src, dst);

    const int gemmBlocks     = (NN + 127) / 128;        // 391
    const int nodeWarpBlocks = (NN * 32 + 255) / 256;   // 6250
    const int nodeBlocks     = (NN + 255) / 256;

    // ----- layer 0 (input = x) -----
    gemm_mma_kernel<<<gemmBlocks, 256, SM_TOT>>>(x, 0, Wq, Wk, Wv, Ws, bq, bk, bv, bs);
    attn_kernel<<<nodeWarpBlocks, 256>>>();

    // ----- layer 1 (input = g_h selected in device code) -----
    gemm_mma_kernel<<<gemmBlocks, 256, SM_TOT>>>(nullptr, 1,
        Wq + 128 * 128, Wk + 128 * 128, Wv + 128 * 128, Ws + 128 * 128,
        bq + 128, bk + 128, bv + 128, bs + 128);
    attn_kernel<<<nodeWarpBlocks, 256>>>();

    // ----- pooling + head -----
    count_kernel<<<nodeBlocks, 256>>>(batch);
    pool_kernel<<<nodeBlocks, 128>>>(batch);
    head_kernel<<<1, 640>>>(Wfc, bfc, out);
}

// round 10
// speedup vs baseline: 1.2489x; 1.0161x over previous
#include <cuda_runtime.h>
#include <cuda_bf16.h>
#include <math_constants.h>
#include <cstdint>

// Problem constants
#define NN   50000
#define EE   600000
#define DD   128
#define GG   64
#define NCLS 10

// ---------------- device scratch ----------------
__device__ float g_h   [NN * DD];
__device__ float g_q   [NN * DD];
__device__ float g_k   [NN * DD];
__device__ float g_v   [NN * DD];
__device__ float g_sk  [NN * DD];

__device__ int   g_deg [NN];
__device__ int   g_cur [NN];
__device__ int   g_rowptr[NN + 1];
__device__ int   g_col [EE];
__device__ int   g_aux [128];

__device__ float g_pool[GG * DD];
__device__ int   g_cnt [GG];

// ---------------- init ----------------
__global__ void init_kernel() {
    int i = blockIdx.x * blockDim.x + threadIdx.x;
    if (i < NN) { g_deg[i] = 0; g_cur[i] = 0; }
    if (i < GG * DD) g_pool[i] = 0.0f;
    if (i < GG) g_cnt[i] = 0;
}

// ---------------- CSR build ----------------
__global__ void hist_kernel(const int* __restrict__ dst) {
    int e = blockIdx.x * blockDim.x + threadIdx.x;
    if (e < EE) atomicAdd(&g_deg[dst[e]], 1);
}
__global__ void scanA_kernel() {
    __shared__ int s[512];
    int t = threadIdx.x;
    int idx = blockIdx.x * 512 + t;
    int val = (idx < NN) ? g_deg[idx] : 0;
    s[t] = val;
    __syncthreads();
    for (int off = 1; off < 512; off <<= 1) {
        int x = (t >= off) ? s[t - off] : 0;
        __syncthreads();
        s[t] += x;
        __syncthreads();
    }
    if (idx < NN) g_rowptr[idx] = s[t];
    if (t == 511) g_aux[blockIdx.x] = s[511];
}
// scanC with folded aux-scan: every block re-scans the 98 block sums in smem.
__global__ void scanC_kernel(int nblocks) {
    __shared__ int aux[128];
    int t = threadIdx.x;
    if (t < 128) {
        int v = (t < nblocks) ? g_aux[t] : 0;
        aux[t] = v;
    }
    __syncthreads();
    // exclusive scan of aux in-place (Hillis-Steele on first 128 lanes)
    for (int off = 1; off < 128; off <<= 1) {
        int x = 0;
        if (t < 128 && t >= off) x = aux[t - off];
        __syncthreads();
        if (t < 128) aux[t] += x;
        __syncthreads();
    }
    int blockOff = (blockIdx.x == 0) ? 0 : aux[blockIdx.x - 1];
    int idx = blockIdx.x * 512 + t;
    if (idx < NN) g_rowptr[idx] = g_rowptr[idx] - g_deg[idx] + blockOff;
    if (idx == 0) g_rowptr[NN] = EE;
}
__global__ void scatter_kernel(const int* __restrict__ src, const int* __restrict__ dst) {
    int e = blockIdx.x * blockDim.x + threadIdx.x;
    if (e < EE) {
        int d = dst[e];
        int pos = g_rowptr[d] + atomicAdd(&g_cur[d], 1);
        g_col[pos] = src[e];
    }
}

// ---------------- HMMA GEMM (mma.sync bf16, fp32 accum, hi/lo split) ----------------
static constexpr int STRD   = 136;                  // bf16 elements per row
static constexpr int TILE_B = 128 * STRD * 2;       // 34816
static constexpr int SM_AH   = 0;
static constexpr int SM_AL   = SM_AH + TILE_B;
static constexpr int SM_BH   = SM_AL + TILE_B;      // [k][n] layout
static constexpr int SM_BL   = SM_BH + TILE_B;
static constexpr int SM_BIAS = SM_BL + TILE_B;      // 139264
static constexpr int SM_TOT  = SM_BIAS + 512;       // 139776

__device__ __forceinline__ void split2(float x, __nv_bfloat16& h, __nv_bfloat16& l) {
    h = __float2bfloat16_rn(x);
    l = __float2bfloat16_rn(x - __bfloat162float(h));
}

#define MMA_BF16(d, a0, a1, a2, a3, b0, b1) \
    asm volatile( \
        "mma.sync.aligned.m16n8k16.row.col.f32.bf16.bf16.f32 " \
        "{%0,%1,%2,%3}, {%4,%5,%6,%7}, {%8,%9}, {%0,%1,%2,%3};" \
        : "+f"((d)[0]), "+f"((d)[1]), "+f"((d)[2]), "+f"((d)[3]) \
        : "r"(a0), "r"(a1), "r"(a2), "r"(a3), "r"(b0), "r"(b1))

#define LDMATRIX_X2_T(r0, r1, addr) \
    asm volatile("ldmatrix.sync.aligned.m8n8.x2.trans.shared.b16 {%0,%1}, [%2];" \
                 : "=r"(r0), "=r"(r1) : "r"(addr))

__device__ __forceinline__ uint32_t smem_u32(const void* p) {
    uint32_t a;
    asm("{ .reg .u64 t; cvta.to.shared.u64 t, %1; cvt.u32.u64 %0, t; }" : "=r"(a) : "l"(p));
    return a;
}

__global__ __launch_bounds__(256) void gemm_mma_kernel(
    const float* __restrict__ Ain, int useGh,
    const float* __restrict__ Wq, const float* __restrict__ Wk,
    const float* __restrict__ Wv, const float* __restrict__ Ws,
    const float* __restrict__ bq, const float* __restrict__ bk,
    const float* __restrict__ bv, const float* __restrict__ bs)
{
    extern __shared__ char smem[];
    const float* A = useGh ? (const float*)g_h : Ain;
    const uint32_t sb = smem_u32(smem);
    const int tid  = threadIdx.x;
    const int wid  = tid >> 5;
    const int lane = tid & 31;
    const int grp  = lane >> 2;      // 0..7
    const int qid  = lane & 3;       // 0..3
    const int row0 = blockIdx.x * 128;
    float* bias_s = (float*)(smem + SM_BIAS);

    // ---- A tile: fp32 -> bf16 hi/lo, row-major [m][k], stride 136 ----
    for (int it = 0; it < 16; it++) {
        int idx = it * 256 + tid;
        int r  = idx >> 5;
        int k4 = (idx & 31) * 4;
        float4 a = make_float4(0.f, 0.f, 0.f, 0.f);
        int gr = row0 + r;
        if (gr < NN) a = *(const float4*)(A + (size_t)gr * 128 + k4);
        __nv_bfloat16 h0, h1, h2, h3, l0, l1, l2, l3;
        split2(a.x, h0, l0); split2(a.y, h1, l1);
        split2(a.z, h2, l2); split2(a.w, h3, l3);
        uint32_t off = (uint32_t)(r * STRD + k4) * 2;
        uint2 ph = make_uint2(((uint32_t)__bfloat16_as_ushort(h1) << 16) | __bfloat16_as_ushort(h0),
                              ((uint32_t)__bfloat16_as_ushort(h3) << 16) | __bfloat16_as_ushort(h2));
        uint2 pl = make_uint2(((uint32_t)__bfloat16_as_ushort(l1) << 16) | __bfloat16_as_ushort(l0),
                              ((uint32_t)__bfloat16_as_ushort(l3) << 16) | __bfloat16_as_ushort(l2));
        *(uint2*)(smem + SM_AH + off) = ph;
        *(uint2*)(smem + SM_AL + off) = pl;
    }

    const int m0 = wid * 16;

    for (int which = 0; which < 4; which++) {
        const float* W    = (which == 0) ? Wq : (which == 1) ? Wk : (which == 2) ? Wv : Ws;
        const float* bias = (which == 0) ? bq : (which == 1) ? bk : (which == 2) ? bv : bs;
        float* O          = (which == 0) ? g_q : (which == 1) ? g_k : (which == 2) ? g_v : g_sk;

        __syncthreads();   // prior-iteration mma reads of Bs complete
        // ---- B tile: W[k][n] fp32 -> bf16 hi/lo, [k][n] layout, stride 136 ----
        for (int it = 0; it < 16; it++) {
            int idx = it * 256 + tid;
            int k  = idx >> 5;
            int n4 = (idx & 31) * 4;
            float4 w = *(const float4*)(W + (size_t)k * 128 + n4);
            __nv_bfloat16 h0, h1, h2, h3, l0, l1, l2, l3;
            split2(w.x, h0, l0); split2(w.y, h1, l1);
            split2(w.z, h2, l2); split2(w.w, h3, l3);
            uint32_t off = (uint32_t)(k * STRD + n4) * 2;
            uint2 ph = make_uint2(((uint32_t)__bfloat16_as_ushort(h1) << 16) | __bfloat16_as_ushort(h0),
                                  ((uint32_t)__bfloat16_as_ushort(h3) << 16) | __bfloat16_as_ushort(h2));
            uint2 pl = make_uint2(((uint32_t)__bfloat16_as_ushort(l1) << 16) | __bfloat16_as_ushort(l0),
                                  ((uint32_t)__bfloat16_as_ushort(l3) << 16) | __bfloat16_as_ushort(l2));
            *(uint2*)(smem + SM_BH + off) = ph;
            *(uint2*)(smem + SM_BL + off) = pl;
        }
        if (tid < 128) bias_s[tid] = bias[tid];
        __syncthreads();

        // ---- mma mainloop ----
        float acc[16][4];
        #pragma unroll
        for (int nt = 0; nt < 16; nt++)
            #pragma unroll
            for (int j = 0; j < 4; j++) acc[nt][j] = 0.f;

        const int rl = lane & 15;
        #pragma unroll 1
        for (int k0 = 0; k0 < 8; k0++) {
            const int k = k0 * 16;
            uint32_t aoff0 = (uint32_t)((m0 + grp) * STRD + k + qid * 2) * 2;
            uint32_t aoff1 = aoff0 + 8u * STRD * 2u;
            uint32_t ah0 = *(const uint32_t*)(smem + SM_AH + aoff0);
            uint32_t ah1 = *(const uint32_t*)(smem + SM_AH + aoff1);
            uint32_t ah2 = *(const uint32_t*)(smem + SM_AH + aoff0 + 16);
            uint32_t ah3 = *(const uint32_t*)(smem + SM_AH + aoff1 + 16);
            uint32_t al0 = *(const uint32_t*)(smem + SM_AL + aoff0);
            uint32_t al1 = *(const uint32_t*)(smem + SM_AL + aoff1);
            uint32_t al2 = *(const uint32_t*)(smem + SM_AL + aoff0 + 16);
            uint32_t al3 = *(const uint32_t*)(smem + SM_AL + aoff1 + 16);

            uint32_t browH = sb + SM_BH + (uint32_t)((k + rl) * STRD) * 2;
            uint32_t browL = sb + SM_BL + (uint32_t)((k + rl) * STRD) * 2;

            #pragma unroll
            for (int nt = 0; nt < 16; nt++) {
                uint32_t bh0, bh1, bl0, bl1;
                LDMATRIX_X2_T(bh0, bh1, browH + nt * 16);
                LDMATRIX_X2_T(bl0, bl1, browL + nt * 16);
                MMA_BF16(acc[nt], ah0, ah1, ah2, ah3, bh0, bh1);
                MMA_BF16(acc[nt], ah0, ah1, ah2, ah3, bl0, bl1);
                MMA_BF16(acc[nt], al0, al1, al2, al3, bh0, bh1);
            }
        }

        // ---- epilogue ----
        int r0 = row0 + m0 + grp;
        int r1 = r0 + 8;
        #pragma unroll
        for (int nt = 0; nt < 16; nt++) {
            int c = nt * 8 + qid * 2;
            float b0 = bias_s[c], b1 = bias_s[c + 1];
            if (r0 < NN) {
                float2 o = make_float2(acc[nt][0] + b0, acc[nt][1] + b1);
                *(float2*)(O + (size_t)r0 * 128 + c) = o;
            }
            if (r1 < NN) {
                float2 o = make_float2(acc[nt][2] + b0, acc[nt][3] + b1);
                *(float2*)(O + (size_t)r1 * 128 + c) = o;
            }
        }
    }
}

// ---------------- attention: warp per dst node, online softmax, depth-1 prefetch ----------------
__global__ __launch_bounds__(256) void attn_kernel() {
    int node = (blockIdx.x * blockDim.x + threadIdx.x) >> 5;
    if (node >= NN) return;
    int lane = threadIdx.x & 31;
    const int base = node * 128 + lane * 4;

    float4 q4 = *(const float4*)(&g_q[base]);
    int beg = g_rowptr[node];
    int end = g_rowptr[node + 1];

    float m = -CUDART_INF_F, den = 0.f;
    float a0 = 0.f, a1 = 0.f, a2 = 0.f, a3 = 0.f;

    float4 kC, vC;
    if (beg < end) {
        int s0 = g_col[beg];
        kC = *(const float4*)(&g_k[(size_t)s0 * 128 + lane * 4]);
        vC = *(const float4*)(&g_v[(size_t)s0 * 128 + lane * 4]);
    }

    for (int i = beg; i < end; i++) {
        float4 k4 = kC, v4 = vC;
        int in = i + 1;
        if (in < end) {                       // prefetch next edge while reducing
            int sn = g_col[in];
            kC = *(const float4*)(&g_k[(size_t)sn * 128 + lane * 4]);
            vC = *(const float4*)(&g_v[(size_t)sn * 128 + lane * 4]);
        }
        float p = q4.x * k4.x + q4.y * k4.y + q4.z * k4.z + q4.w * k4.w;
        p += __shfl_xor_sync(0xffffffffu, p, 16);
        p += __shfl_xor_sync(0xffffffffu, p, 8);
        p += __shfl_xor_sync(0xffffffffu, p, 4);
        p += __shfl_xor_sync(0xffffffffu, p, 2);
        p += __shfl_xor_sync(0xffffffffu, p, 1);
        float score = p * 0.08838834764831845f;  // 1/sqrt(128)
        float nm = fmaxf(m, score);
        float sc = __expf(m - nm);
        float w  = __expf(score - nm);
        den = den * sc + w;
        a0 = fmaf(a0, sc, w * v4.x);
        a1 = fmaf(a1, sc, w * v4.y);
        a2 = fmaf(a2, sc, w * v4.z);
        a3 = fmaf(a3, sc, w * v4.w);
        m = nm;
    }

    float inv = (den > 0.f) ? (1.0f / den) : 0.0f;
    float4 sk4 = *(const float4*)(&g_sk[base]);
    float4 o;
    o.x = fmaxf(fmaf(a0, inv, sk4.x), 0.f);
    o.y = fmaxf(fmaf(a1, inv, sk4.y), 0.f);
    o.z = fmaxf(fmaf(a2, inv, sk4.z), 0.f);
    o.w = fmaxf(fmaf(a3, inv, sk4.w), 0.f);
    *(float4*)(&g_h[base]) = o;
}

// ---------------- pooling ----------------
__global__ void count_kernel(const int* __restrict__ batch) {
    int n = blockIdx.x * blockDim.x + threadIdx.x;
    if (n < NN) atomicAdd(&g_cnt[batch[n]], 1);
}
__global__ __launch_bounds__(128) void pool_kernel(const int* __restrict__ batch) {
    int t = threadIdx.x;
    int n0 = blockIdx.x * 256;
    int nend = min(n0 + 256, NN);
    int gcur = -1;
    float acc = 0.f;
    for (int n = n0; n < nend; n++) {
        int g = batch[n];
        if (g != gcur) {
            if (gcur >= 0) atomicAdd(&g_pool[gcur * 128 + t], acc);
            gcur = g; acc = 0.f;
        }
        acc += g_h[(size_t)n * 128 + t];
    }
    if (gcur >= 0) atomicAdd(&g_pool[gcur * 128 + t], acc);
}

// ---------------- head ----------------
__global__ __launch_bounds__(640) void head_kernel(
    const float* __restrict__ Wfc, const float* __restrict__ bfc, float* __restrict__ out)
{
    __shared__ float logits[GG][NCLS];
    __shared__ float rmax[GG], rlse[GG];
    int t = threadIdx.x;
    int g = t / NCLS, c = t % NCLS;

    float cnt = (float)g_cnt[g];
    if (cnt < 1.f) cnt = 1.f;
    float s = 0.f;
    for (int d = 0; d < 128; d++)
        s += g_pool[g * 128 + d] * Wfc[d * NCLS + c];
    s = s / cnt + bfc[c];
    logits[g][c] = s;
    __syncthreads();

    if (t < GG) {
        float m = -CUDART_INF_F;
        for (int j = 0; j < NCLS; j++) m = fmaxf(m, logits[t][j]);
        float l = 0.f;
        for (int j = 0; j < NCLS; j++) l += expf(logits[t][j] - m);
        rmax[t] = m;
        rlse[t] = logf(l);
    }
    __syncthreads();
    out[g * NCLS + c] = logits[g][c] - rmax[g] - rlse[g];
}

// ---------------- launch ----------------
extern "C" void kernel_launch(void* const* d_in, const int* in_sizes, int n_in,
                              void* d_out, int out_size)
{
    const float* x   = (const float*)d_in[0];
    const int* eidx  = (const int*)d_in[1];
    const int* batch = (const int*)d_in[2];
    const float* Wq  = (const float*)d_in[3];
    const float* bq  = (const float*)d_in[4];
    const float* Wk  = (const float*)d_in[5];
    const float* bk  = (const float*)d_in[6];
    const float* Wv  = (const float*)d_in[7];
    const float* bv  = (const float*)d_in[8];
    const float* Ws  = (const float*)d_in[9];
    const float* bs  = (const float*)d_in[10];
    const float* Wfc = (const float*)d_in[11];
    const float* bfc = (const float*)d_in[12];
    float* out = (float*)d_out;

    const int* src = eidx;        // row 0
    const int* dst = eidx + EE;   // row 1

    // one-time infra (host-side handles only; captured graph is identical per call)
    static cudaStream_t s2 = nullptr;
    static cudaEvent_t evFork = nullptr, evJoin = nullptr;
    static bool attrSet = false;
    if (!s2) {
        cudaStreamCreateWithFlags(&s2, cudaStreamNonBlocking);
        cudaEventCreateWithFlags(&evFork, cudaEventDisableTiming);
        cudaEventCreateWithFlags(&evJoin, cudaEventDisableTiming);
    }
    if (!attrSet) {
        cudaFuncSetAttribute(gemm_mma_kernel,
                             cudaFuncAttributeMaxDynamicSharedMemorySize, SM_TOT);
        attrSet = true;
    }

    const int scanBlocks = (NN + 511) / 512;   // 98
    const int gemmBlocks     = (NN + 127) / 128;        // 391
    const int nodeWarpBlocks = (NN * 32 + 255) / 256;   // 6250
    const int nodeBlocks     = (NN + 255) / 256;

    // ---- fork: CSR build + counts on side stream, overlapped with layer-0 GEMM ----
    cudaEventRecord(evFork, 0);
    cudaStreamWaitEvent(s2, evFork, 0);

    init_kernel<<<(NN + 255) / 256, 256, 0, s2>>>();
    hist_kernel<<<(EE + 255) / 256, 256, 0, s2>>>(dst);
    scanA_kernel<<<scanBlocks, 512, 0, s2>>>();
    scanC_kernel<<<scanBlocks, 512, 0, s2>>>(scanBlocks);
    scatter_kernel<<<(EE + 255) / 256, 256, 0, s2>>>(src, dst);
    count_kernel<<<nodeBlocks, 256, 0, s2>>>(batch);
    cudaEventRecord(evJoin, s2);

    // ----- layer 0 GEMM (independent of CSR) -----
    gemm_mma_kernel<<<gemmBlocks, 256, SM_TOT>>>(x, 0, Wq, Wk, Wv, Ws, bq, bk, bv, bs);

    // join: attention needs CSR
    cudaStreamWaitEvent(0, evJoin, 0);
    attn_kernel<<<nodeWarpBlocks, 256>>>();

    // ----- layer 1 -----
    gemm_mma_kernel<<<gemmBlocks, 256, SM_TOT>>>(nullptr, 1,
        Wq + 128 * 128, Wk + 128 * 128, Wv + 128 * 128, Ws + 128 * 128,
        bq + 128, bk + 128, bv + 128, bs + 128);
    attn_kernel<<<nodeWarpBlocks, 256>>>();

    // ----- pooling + head -----
    pool_kernel<<<nodeBlocks, 128>>>(batch);
    head_kernel<<<1, 640>>>(Wfc, bfc, out);
}

// round 11
// speedup vs baseline: 1.4340x; 1.1481x over previous
#include <cuda_runtime.h>
#include <cuda_bf16.h>
#include <math_constants.h>
#include <cstdint>

// Problem constants
#define NN   50000
#define EE   600000
#define DD   128
#define GG   64
#define NCLS 10

static constexpr int STRD   = 136;                  // bf16 elements per row
static constexpr int MATEL  = 128 * STRD;           // 17408 bf16 per matrix image

// ---------------- device scratch ----------------
__device__ float g_h   [NN * DD];
__device__ float g_q   [NN * DD];
__device__ float g_k   [NN * DD];
__device__ float g_v   [NN * DD];
__device__ float g_sk  [NN * DD];

__device__ __align__(16) __nv_bfloat16 g_wbh[8 * MATEL];  // weight hi images (L*4 matrices)
__device__ __align__(16) __nv_bfloat16 g_wbl[8 * MATEL];  // weight lo images

__device__ int   g_deg [NN];
__device__ int   g_cur [NN];
__device__ int   g_rowptr[NN + 1];
__device__ int   g_col [EE];
__device__ int   g_aux [128];

__device__ float g_pool[GG * DD];
__device__ int   g_cnt [GG];

// ---------------- init ----------------
__global__ void init_kernel() {
    int i = blockIdx.x * blockDim.x + threadIdx.x;
    if (i < NN) { g_deg[i] = 0; g_cur[i] = 0; }
    if (i < GG * DD) g_pool[i] = 0.0f;
    if (i < GG) g_cnt[i] = 0;
}

// ---------------- CSR build ----------------
__global__ void hist_kernel(const int* __restrict__ dst) {
    int e = blockIdx.x * blockDim.x + threadIdx.x;
    if (e < EE) atomicAdd(&g_deg[dst[e]], 1);
}
__global__ void scanA_kernel() {
    __shared__ int s[512];
    int t = threadIdx.x;
    int idx = blockIdx.x * 512 + t;
    int val = (idx < NN) ? g_deg[idx] : 0;
    s[t] = val;
    __syncthreads();
    for (int off = 1; off < 512; off <<= 1) {
        int x = (t >= off) ? s[t - off] : 0;
        __syncthreads();
        s[t] += x;
        __syncthreads();
    }
    if (idx < NN) g_rowptr[idx] = s[t];
    if (t == 511) g_aux[blockIdx.x] = s[511];
}
__global__ void scanC_kernel(int nblocks) {
    __shared__ int aux[128];
    int t = threadIdx.x;
    if (t < 128) aux[t] = (t < nblocks) ? g_aux[t] : 0;
    __syncthreads();
    for (int off = 1; off < 128; off <<= 1) {
        int x = 0;
        if (t < 128 && t >= off) x = aux[t - off];
        __syncthreads();
        if (t < 128) aux[t] += x;
        __syncthreads();
    }
    int blockOff = (blockIdx.x == 0) ? 0 : aux[blockIdx.x - 1];
    int idx = blockIdx.x * 512 + t;
    if (idx < NN) g_rowptr[idx] = g_rowptr[idx] - g_deg[idx] + blockOff;
    if (idx == 0) g_rowptr[NN] = EE;
}
__global__ void scatter_kernel(const int* __restrict__ src, const int* __restrict__ dst) {
    int e = blockIdx.x * blockDim.x + threadIdx.x;
    if (e < EE) {
        int d = dst[e];
        int pos = g_rowptr[d] + atomicAdd(&g_cur[d], 1);
        g_col[pos] = src[e];
    }
}

// ---------------- weight prep: fp32 -> bf16 hi/lo images in SMEM layout ----------------
__device__ __forceinline__ void split2(float x, __nv_bfloat16& h, __nv_bfloat16& l) {
    h = __float2bfloat16_rn(x);
    l = __float2bfloat16_rn(x - __bfloat162float(h));
}
// grid.x = 8: layer = bx>>2, which = bx&3
__global__ __launch_bounds__(256) void prep_weights_kernel(
    const float* __restrict__ Wq, const float* __restrict__ Wk,
    const float* __restrict__ Wv, const float* __restrict__ Ws)
{
    int layer = blockIdx.x >> 2;
    int which = blockIdx.x & 3;
    const float* W = (which == 0) ? Wq : (which == 1) ? Wk : (which == 2) ? Wv : Ws;
    W += layer * 128 * 128;
    size_t outBase = (size_t)blockIdx.x * MATEL;
    for (int idx = threadIdx.x; idx < 128 * 128; idx += 256) {
        int k = idx >> 7, n = idx & 127;
        __nv_bfloat16 h, l;
        split2(W[idx], h, l);
        size_t o = outBase + (size_t)k * STRD + n;
        g_wbh[o] = h;
        g_wbl[o] = l;
    }
}

// ---------------- HMMA GEMM (mma.sync bf16, fp32 accum, hi/lo split) ----------------
static constexpr int TILE_B = MATEL * 2;            // 34816 bytes
static constexpr int SM_AH   = 0;
static constexpr int SM_AL   = SM_AH + TILE_B;
static constexpr int SM_BH   = SM_AL + TILE_B;
static constexpr int SM_BL   = SM_BH + TILE_B;
static constexpr int SM_BIAS = SM_BL + TILE_B;      // 139264
static constexpr int SM_TOT  = SM_BIAS + 512;       // 139776

#define MMA_BF16(d, a0, a1, a2, a3, b0, b1) \
    asm volatile( \
        "mma.sync.aligned.m16n8k16.row.col.f32.bf16.bf16.f32 " \
        "{%0,%1,%2,%3}, {%4,%5,%6,%7}, {%8,%9}, {%0,%1,%2,%3};" \
        : "+f"((d)[0]), "+f"((d)[1]), "+f"((d)[2]), "+f"((d)[3]) \
        : "r"(a0), "r"(a1), "r"(a2), "r"(a3), "r"(b0), "r"(b1))

#define LDMATRIX_X2_T(r0, r1, addr) \
    asm volatile("ldmatrix.sync.aligned.m8n8.x2.trans.shared.b16 {%0,%1}, [%2];" \
                 : "=r"(r0), "=r"(r1) : "r"(addr))

__device__ __forceinline__ uint32_t smem_u32(const void* p) {
    uint32_t a;
    asm("{ .reg .u64 t; cvta.to.shared.u64 t, %1; cvt.u32.u64 %0, t; }" : "=r"(a) : "l"(p));
    return a;
}

__global__ __launch_bounds__(256) void gemm_mma_kernel(
    const float* __restrict__ Ain, int useGh, int layer,
    const float* __restrict__ bq, const float* __restrict__ bk,
    const float* __restrict__ bv, const float* __restrict__ bs)
{
    extern __shared__ char smem[];
    const float* A = useGh ? (const float*)g_h : Ain;
    const uint32_t sb = smem_u32(smem);
    const int tid  = threadIdx.x;
    const int wid  = tid >> 5;
    const int lane = tid & 31;
    const int grp  = lane >> 2;
    const int qid  = lane & 3;
    const int row0 = blockIdx.x * 128;
    float* bias_s = (float*)(smem + SM_BIAS);

    // ---- A tile: fp32 -> bf16 hi/lo, row-major [m][k], stride 136 ----
    for (int it = 0; it < 16; it++) {
        int idx = it * 256 + tid;
        int r  = idx >> 5;
        int k4 = (idx & 31) * 4;
        float4 a = make_float4(0.f, 0.f, 0.f, 0.f);
        int gr = row0 + r;
        if (gr < NN) a = *(const float4*)(A + (size_t)gr * 128 + k4);
        __nv_bfloat16 h0, h1, h2, h3, l0, l1, l2, l3;
        split2(a.x, h0, l0); split2(a.y, h1, l1);
        split2(a.z, h2, l2); split2(a.w, h3, l3);
        uint32_t off = (uint32_t)(r * STRD + k4) * 2;
        uint2 ph = make_uint2(((uint32_t)__bfloat16_as_ushort(h1) << 16) | __bfloat16_as_ushort(h0),
                              ((uint32_t)__bfloat16_as_ushort(h3) << 16) | __bfloat16_as_ushort(h2));
        uint2 pl = make_uint2(((uint32_t)__bfloat16_as_ushort(l1) << 16) | __bfloat16_as_ushort(l0),
                              ((uint32_t)__bfloat16_as_ushort(l3) << 16) | __bfloat16_as_ushort(l2));
        *(uint2*)(smem + SM_AH + off) = ph;
        *(uint2*)(smem + SM_AL + off) = pl;
    }

    const int m0 = wid * 16;

    for (int which = 0; which < 4; which++) {
        const float* bias = (which == 0) ? bq : (which == 1) ? bk : (which == 2) ? bv : bs;
        float* O          = (which == 0) ? g_q : (which == 1) ? g_k : (which == 2) ? g_v : g_sk;

        __syncthreads();   // prior-iteration mma reads of Bs complete
        // ---- B tiles: straight float4 copy of precomputed images (L2-resident) ----
        {
            const char* srcH = (const char*)(g_wbh + (size_t)(layer * 4 + which) * MATEL);
            const char* srcL = (const char*)(g_wbl + (size_t)(layer * 4 + which) * MATEL);
            #pragma unroll
            for (int it = 0; it < 9; it++) {       // 9*256 = 2304 >= 2176
                int f = it * 256 + tid;
                if (f < TILE_B / 16) {
                    *(float4*)(smem + SM_BH + f * 16) = *(const float4*)(srcH + f * 16);
                    *(float4*)(smem + SM_BL + f * 16) = *(const float4*)(srcL + f * 16);
                }
            }
        }
        if (tid < 128) bias_s[tid] = bias[tid];
        __syncthreads();

        // ---- mma mainloop ----
        float acc[16][4];
        #pragma unroll
        for (int nt = 0; nt < 16; nt++)
            #pragma unroll
            for (int j = 0; j < 4; j++) acc[nt][j] = 0.f;

        const int rl = lane & 15;
        #pragma unroll 1
        for (int k0 = 0; k0 < 8; k0++) {
            const int k = k0 * 16;
            uint32_t aoff0 = (uint32_t)((m0 + grp) * STRD + k + qid * 2) * 2;
            uint32_t aoff1 = aoff0 + 8u * STRD * 2u;
            uint32_t ah0 = *(const uint32_t*)(smem + SM_AH + aoff0);
            uint32_t ah1 = *(const uint32_t*)(smem + SM_AH + aoff1);
            uint32_t ah2 = *(const uint32_t*)(smem + SM_AH + aoff0 + 16);
            uint32_t ah3 = *(const uint32_t*)(smem + SM_AH + aoff1 + 16);
            uint32_t al0 = *(const uint32_t*)(smem + SM_AL + aoff0);
            uint32_t al1 = *(const uint32_t*)(smem + SM_AL + aoff1);
            uint32_t al2 = *(const uint32_t*)(smem + SM_AL + aoff0 + 16);
            uint32_t al3 = *(const uint32_t*)(smem + SM_AL + aoff1 + 16);

            uint32_t browH = sb + SM_BH + (uint32_t)((k + rl) * STRD) * 2;
            uint32_t browL = sb + SM_BL + (uint32_t)((k + rl) * STRD) * 2;

            #pragma unroll
            for (int nt = 0; nt < 16; nt++) {
                uint32_t bh0, bh1, bl0, bl1;
                LDMATRIX_X2_T(bh0, bh1, browH + nt * 16);
                LDMATRIX_X2_T(bl0, bl1, browL + nt * 16);
                MMA_BF16(acc[nt], ah0, ah1, ah2, ah3, bh0, bh1);
                MMA_BF16(acc[nt], ah0, ah1, ah2, ah3, bl0, bl1);
                MMA_BF16(acc[nt], al0, al1, al2, al3, bh0, bh1);
            }
        }

        // ---- epilogue ----
        int r0 = row0 + m0 + grp;
        int r1 = r0 + 8;
        #pragma unroll
        for (int nt = 0; nt < 16; nt++) {
            int c = nt * 8 + qid * 2;
            float b0 = bias_s[c], b1 = bias_s[c + 1];
            if (r0 < NN) {
                float2 o = make_float2(acc[nt][0] + b0, acc[nt][1] + b1);
                *(float2*)(O + (size_t)r0 * 128 + c) = o;
            }
            if (r1 < NN) {
                float2 o = make_float2(acc[nt][2] + b0, acc[nt][3] + b1);
                *(float2*)(O + (size_t)r1 * 128 + c) = o;
            }
        }
    }
}

// ---------------- attention: warp per dst node, online softmax, 2 edges/step ----------------
__device__ __forceinline__ float warp_red(float p) {
    p += __shfl_xor_sync(0xffffffffu, p, 16);
    p += __shfl_xor_sync(0xffffffffu, p, 8);
    p += __shfl_xor_sync(0xffffffffu, p, 4);
    p += __shfl_xor_sync(0xffffffffu, p, 2);
    p += __shfl_xor_sync(0xffffffffu, p, 1);
    return p;
}

__global__ __launch_bounds__(256) void attn_kernel() {
    int node = (blockIdx.x * blockDim.x + threadIdx.x) >> 5;
    if (node >= NN) return;
    int lane = threadIdx.x & 31;
    const int base = node * 128 + lane * 4;
    const int lo4  = lane * 4;

    float4 q4 = *(const float4*)(&g_q[base]);
    int beg = g_rowptr[node];
    int end = g_rowptr[node + 1];

    float m = -CUDART_INF_F, den = 0.f;
    float a0 = 0.f, a1 = 0.f, a2 = 0.f, a3 = 0.f;
    const float SCALE = 0.08838834764831845f;   // 1/sqrt(128)

    int i = beg;
    for (; i + 2 <= end; i += 2) {
        int s0 = g_col[i], s1 = g_col[i + 1];
        float4 k0 = *(const float4*)(&g_k[(size_t)s0 * 128 + lo4]);
        float4 k1 = *(const float4*)(&g_k[(size_t)s1 * 128 + lo4]);
        float4 v0 = *(const float4*)(&g_v[(size_t)s0 * 128 + lo4]);
        float4 v1 = *(const float4*)(&g_v[(size_t)s1 * 128 + lo4]);
        float p0 = q4.x * k0.x + q4.y * k0.y + q4.z * k0.z + q4.w * k0.w;
        float p1 = q4.x * k1.x + q4.y * k1.y + q4.z * k1.z + q4.w * k1.w;
        p0 = warp_red(p0);
        p1 = warp_red(p1);
        float sc0 = p0 * SCALE, sc1 = p1 * SCALE;
        float nm = fmaxf(m, fmaxf(sc0, sc1));
        float cm = __expf(m - nm);
        float w0 = __expf(sc0 - nm);
        float w1 = __expf(sc1 - nm);
        den = den * cm + w0 + w1;
        a0 = fmaf(a0, cm, fmaf(w0, v0.x, w1 * v1.x));
        a1 = fmaf(a1, cm, fmaf(w0, v0.y, w1 * v1.y));
        a2 = fmaf(a2, cm, fmaf(w0, v0.z, w1 * v1.z));
        a3 = fmaf(a3, cm, fmaf(w0, v0.w, w1 * v1.w));
        m = nm;
    }
    if (i < end) {
        int s0 = g_col[i];
        float4 k0 = *(const float4*)(&g_k[(size_t)s0 * 128 + lo4]);
        float4 v0 = *(const float4*)(&g_v[(size_t)s0 * 128 + lo4]);
        float p0 = q4.x * k0.x + q4.y * k0.y + q4.z * k0.z + q4.w * k0.w;
        p0 = warp_red(p0);
        float sc0 = p0 * SCALE;
        float nm = fmaxf(m, sc0);
        float cm = __expf(m - nm);
        float w0 = __expf(sc0 - nm);
        den = den * cm + w0;
        a0 = fmaf(a0, cm, w0 * v0.x);
        a1 = fmaf(a1, cm, w0 * v0.y);
        a2 = fmaf(a2, cm, w0 * v0.z);
        a3 = fmaf(a3, cm, w0 * v0.w);
        m = nm;
    }

    float inv = (den > 0.f) ? (1.0f / den) : 0.0f;
    float4 sk4 = *(const float4*)(&g_sk[base]);
    float4 o;
    o.x = fmaxf(fmaf(a0, inv, sk4.x), 0.f);
    o.y = fmaxf(fmaf(a1, inv, sk4.y), 0.f);
    o.z = fmaxf(fmaf(a2, inv, sk4.z), 0.f);
    o.w = fmaxf(fmaf(a3, inv, sk4.w), 0.f);
    *(float4*)(&g_h[base]) = o;
}

// ---------------- pooling ----------------
__global__ void count_kernel(const int* __restrict__ batch) {
    int n = blockIdx.x * blockDim.x + threadIdx.x;
    if (n < NN) atomicAdd(&g_cnt[batch[n]], 1);
}
__global__ __launch_bounds__(128) void pool_kernel(const int* __restrict__ batch) {
    int t = threadIdx.x;
    int n0 = blockIdx.x * 256;
    int nend = min(n0 + 256, NN);
    int gcur = -1;
    float acc = 0.f;
    for (int n = n0; n < nend; n++) {
        int g = batch[n];
        if (g != gcur) {
            if (gcur >= 0) atomicAdd(&g_pool[gcur * 128 + t], acc);
            gcur = g; acc = 0.f;
        }
        acc += g_h[(size_t)n * 128 + t];
    }
    if (gcur >= 0) atomicAdd(&g_pool[gcur * 128 + t], acc);
}

// ---------------- head ----------------
__global__ __launch_bounds__(640) void head_kernel(
    const float* __restrict__ Wfc, const float* __restrict__ bfc, float* __restrict__ out)
{
    __shared__ float logits[GG][NCLS];
    __shared__ float rmax[GG], rlse[GG];
    int t = threadIdx.x;
    int g = t / NCLS, c = t % NCLS;

    float cnt = (float)g_cnt[g];
    if (cnt < 1.f) cnt = 1.f;
    float s = 0.f;
    for (int d = 0; d < 128; d++)
        s += g_pool[g * 128 + d] * Wfc[d * NCLS + c];
    s = s / cnt + bfc[c];
    logits[g][c] = s;
    __syncthreads();

    if (t < GG) {
        float m = -CUDART_INF_F;
        for (int j = 0; j < NCLS; j++) m = fmaxf(m, logits[t][j]);
        float l = 0.f;
        for (int j = 0; j < NCLS; j++) l += expf(logits[t][j] - m);
        rmax[t] = m;
        rlse[t] = logf(l);
    }
    __syncthreads();
    out[g * NCLS + c] = logits[g][c] - rmax[g] - rlse[g];
}

// ---------------- launch ----------------
extern "C" void kernel_launch(void* const* d_in, const int* in_sizes, int n_in,
                              void* d_out, int out_size)
{
    const float* x   = (const float*)d_in[0];
    const int* eidx  = (const int*)d_in[1];
    const int* batch = (const int*)d_in[2];
    const float* Wq  = (const float*)d_in[3];
    const float* bq  = (const float*)d_in[4];
    const float* Wk  = (const float*)d_in[5];
    const float* bk  = (const float*)d_in[6];
    const float* Wv  = (const float*)d_in[7];
    const float* bv  = (const float*)d_in[8];
    const float* Ws  = (const float*)d_in[9];
    const float* bs  = (const float*)d_in[10];
    const float* Wfc = (const float*)d_in[11];
    const float* bfc = (const float*)d_in[12];
    float* out = (float*)d_out;

    const int* src = eidx;        // row 0
    const int* dst = eidx + EE;   // row 1

    static cudaStream_t s2 = nullptr;
    static cudaEvent_t evFork = nullptr, evJoin = nullptr;
    static bool attrSet = false;
    if (!s2) {
        cudaStreamCreateWithFlags(&s2, cudaStreamNonBlocking);
        cudaEventCreateWithFlags(&evFork, cudaEventDisableTiming);
        cudaEventCreateWithFlags(&evJoin, cudaEventDisableTiming);
    }
    if (!attrSet) {
        cudaFuncSetAttribute(gemm_mma_kernel,
                             cudaFuncAttributeMaxDynamicSharedMemorySize, SM_TOT);
        attrSet = true;
    }

    const int scanBlocks = (NN + 511) / 512;   // 98
    const int gemmBlocks     = (NN + 127) / 128;        // 391
    const int nodeWarpBlocks = (NN * 32 + 255) / 256;   // 6250
    const int nodeBlocks     = (NN + 255) / 256;

    // ---- fork: CSR build + counts on side stream ----
    cudaEventRecord(evFork, 0);
    cudaStreamWaitEvent(s2, evFork, 0);

    init_kernel<<<(NN + 255) / 256, 256, 0, s2>>>();
    hist_kernel<<<(EE + 255) / 256, 256, 0, s2>>>(dst);
    scanA_kernel<<<scanBlocks, 512, 0, s2>>>();
    scanC_kernel<<<scanBlocks, 512, 0, s2>>>(scanBlocks);
    scatter_kernel<<<(EE + 255) / 256, 256, 0, s2>>>(src, dst);
    count_kernel<<<nodeBlocks, 256, 0, s2>>>(batch);
    cudaEventRecord(evJoin, s2);

    // ----- main stream: weight prep, then layer 0 GEMM -----
    prep_weights_kernel<<<8, 256>>>(Wq, Wk, Wv, Ws);
    gemm_mma_kernel<<<gemmBlocks, 256, SM_TOT>>>(x, 0, 0, bq, bk, bv, bs);

    // join: attention needs CSR
    cudaStreamWaitEvent(0, evJoin, 0);
    attn_kernel<<<nodeWarpBlocks, 256>>>();

    // ----- layer 1 -----
    gemm_mma_kernel<<<gemmBlocks, 256, SM_TOT>>>(nullptr, 1, 1,
        bq + 128, bk + 128, bv + 128, bs + 128);
    attn_kernel<<<nodeWarpBlocks, 256>>>();

    // ----- pooling + head -----
    pool_kernel<<<nodeBlocks, 128>>>(batch);
    head_kernel<<<1, 640>>>(Wfc, bfc, out);
}

// round 12
// speedup vs baseline: 1.4833x; 1.0344x over previous
#include <cuda_runtime.h>
#include <cuda_bf16.h>
#include <math_constants.h>
#include <cstdint>

// Problem constants
#define NN   50000
#define EE   600000
#define DD   128
#define GG   64
#define NCLS 10

static constexpr int STRD   = 136;                  // bf16 elements per row
static constexpr int MATEL  = 128 * STRD;           // 17408 bf16 per matrix image

// ---------------- device scratch ----------------
__device__ float g_h   [NN * DD];
__device__ float g_q   [NN * DD];
__device__ float g_k   [NN * DD];
__device__ float g_v   [NN * DD];
__device__ float g_sk  [NN * DD];

__device__ __align__(16) __nv_bfloat16 g_wbh[8 * MATEL];  // weight hi images
__device__ __align__(16) __nv_bfloat16 g_wbl[8 * MATEL];  // weight lo images

__device__ int   g_deg [NN];
__device__ int   g_cur [NN];
__device__ int   g_rowptr[NN + 1];
__device__ int   g_col [EE];
__device__ int   g_aux [128];

__device__ float g_pool[GG * DD];
__device__ int   g_cnt [GG];

// ---------------- init ----------------
__global__ void init_kernel() {
    int i = blockIdx.x * blockDim.x + threadIdx.x;
    if (i < NN) { g_deg[i] = 0; g_cur[i] = 0; }
    if (i < GG * DD) g_pool[i] = 0.0f;
    if (i < GG) g_cnt[i] = 0;
}

// ---------------- CSR build ----------------
__global__ void hist_kernel(const int* __restrict__ dst) {
    int e = blockIdx.x * blockDim.x + threadIdx.x;
    if (e < EE) atomicAdd(&g_deg[dst[e]], 1);
}
__global__ void scanA_kernel() {
    __shared__ int s[512];
    int t = threadIdx.x;
    int idx = blockIdx.x * 512 + t;
    int val = (idx < NN) ? g_deg[idx] : 0;
    s[t] = val;
    __syncthreads();
    for (int off = 1; off < 512; off <<= 1) {
        int x = (t >= off) ? s[t - off] : 0;
        __syncthreads();
        s[t] += x;
        __syncthreads();
    }
    if (idx < NN) g_rowptr[idx] = s[t];
    if (t == 511) g_aux[blockIdx.x] = s[511];
}
__global__ void scanC_kernel(int nblocks) {
    __shared__ int aux[128];
    int t = threadIdx.x;
    if (t < 128) aux[t] = (t < nblocks) ? g_aux[t] : 0;
    __syncthreads();
    for (int off = 1; off < 128; off <<= 1) {
        int x = 0;
        if (t < 128 && t >= off) x = aux[t - off];
        __syncthreads();
        if (t < 128) aux[t] += x;
        __syncthreads();
    }
    int blockOff = (blockIdx.x == 0) ? 0 : aux[blockIdx.x - 1];
    int idx = blockIdx.x * 512 + t;
    if (idx < NN) g_rowptr[idx] = g_rowptr[idx] - g_deg[idx] + blockOff;
    if (idx == 0) g_rowptr[NN] = EE;
}
__global__ void scatter_kernel(const int* __restrict__ src, const int* __restrict__ dst) {
    int e = blockIdx.x * blockDim.x + threadIdx.x;
    if (e < EE) {
        int d = dst[e];
        int pos = g_rowptr[d] + atomicAdd(&g_cur[d], 1);
        g_col[pos] = src[e];
    }
}

// ---------------- weight prep ----------------
__device__ __forceinline__ void split2(float x, __nv_bfloat16& h, __nv_bfloat16& l) {
    h = __float2bfloat16_rn(x);
    l = __float2bfloat16_rn(x - __bfloat162float(h));
}
__global__ __launch_bounds__(256) void prep_weights_kernel(
    const float* __restrict__ Wq, const float* __restrict__ Wk,
    const float* __restrict__ Wv, const float* __restrict__ Ws)
{
    int layer = blockIdx.x >> 2;
    int which = blockIdx.x & 3;
    const float* W = (which == 0) ? Wq : (which == 1) ? Wk : (which == 2) ? Wv : Ws;
    W += layer * 128 * 128;
    size_t outBase = (size_t)blockIdx.x * MATEL;
    for (int idx = threadIdx.x; idx < 128 * 128; idx += 256) {
        int k = idx >> 7, n = idx & 127;
        __nv_bfloat16 h, l;
        split2(W[idx], h, l);
        size_t o = outBase + (size_t)k * STRD + n;
        g_wbh[o] = h;
        g_wbl[o] = l;
    }
}

// ---------------- HMMA GEMM ----------------
static constexpr int TILE_B = MATEL * 2;            // 34816 bytes (one hi or lo image)
static constexpr int SM_AH   = 0;
static constexpr int SM_AL   = SM_AH + TILE_B;      // 34816
static constexpr int SM_B0   = 69632;               // buffer0: [H|L] = 69632
static constexpr int SM_B1   = 139264;              // buffer1: [H|L]
static constexpr int SM_BIAS = 208896;              // 4 x 128 floats = 2048
static constexpr int SM_TOT  = 210944;

#define MMA_BF16(d, a0, a1, a2, a3, b0, b1) \
    asm volatile( \
        "mma.sync.aligned.m16n8k16.row.col.f32.bf16.bf16.f32 " \
        "{%0,%1,%2,%3}, {%4,%5,%6,%7}, {%8,%9}, {%0,%1,%2,%3};" \
        : "+f"((d)[0]), "+f"((d)[1]), "+f"((d)[2]), "+f"((d)[3]) \
        : "r"(a0), "r"(a1), "r"(a2), "r"(a3), "r"(b0), "r"(b1))

#define LDMATRIX_X4_T(r0, r1, r2, r3, addr) \
    asm volatile("ldmatrix.sync.aligned.m8n8.x4.trans.shared.b16 {%0,%1,%2,%3}, [%4];" \
                 : "=r"(r0), "=r"(r1), "=r"(r2), "=r"(r3) : "r"(addr))

#define CP_ASYNC16(dst, src) \
    asm volatile("cp.async.cg.shared.global [%0], [%1], 16;" :: "r"(dst), "l"(src))
#define CP_COMMIT()  asm volatile("cp.async.commit_group;" ::: "memory")
#define CP_WAIT0()   asm volatile("cp.async.wait_group 0;" ::: "memory")

__device__ __forceinline__ uint32_t smem_u32(const void* p) {
    uint32_t a;
    asm("{ .reg .u64 t; cvta.to.shared.u64 t, %1; cvt.u32.u64 %0, t; }" : "=r"(a) : "l"(p));
    return a;
}

__device__ __forceinline__ void issue_b_copy(uint32_t dstBase, int mat, int tid) {
    const char* sH = (const char*)(g_wbh + (size_t)mat * MATEL);
    const char* sL = (const char*)(g_wbl + (size_t)mat * MATEL);
    #pragma unroll
    for (int it = 0; it < 17; it++) {            // 17*256 = 4352 = 2*TILE_B/16
        int f = it * 256 + tid;
        const char* src = (f < 2176) ? (sH + (size_t)f * 16)
                                     : (sL + (size_t)(f - 2176) * 16);
        CP_ASYNC16(dstBase + f * 16, src);
    }
}

__global__ __launch_bounds__(256) void gemm_mma_kernel(
    const float* __restrict__ Ain, int useGh, int layer,
    const float* __restrict__ bq, const float* __restrict__ bk,
    const float* __restrict__ bv, const float* __restrict__ bs)
{
    extern __shared__ char smem[];
    const float* A = useGh ? (const float*)g_h : Ain;
    const uint32_t sb = smem_u32(smem);
    const int tid  = threadIdx.x;
    const int wid  = tid >> 5;
    const int lane = tid & 31;
    const int grp  = lane >> 2;
    const int qid  = lane & 3;
    const int row0 = blockIdx.x * 128;
    float* bias_s = (float*)(smem + SM_BIAS);

    // kick off async copy of B(which=0) immediately
    issue_b_copy(sb + SM_B0, layer * 4 + 0, tid);
    CP_COMMIT();

    // biases for all 4 outputs
    if (tid < 128) {
        bias_s[tid]       = bq[tid];
        bias_s[tid + 128] = bk[tid];
        bias_s[tid + 256] = bv[tid];
        bias_s[tid + 384] = bs[tid];
    }

    // ---- A tile: fp32 -> bf16 hi/lo, row-major [m][k], stride 136 ----
    for (int it = 0; it < 16; it++) {
        int idx = it * 256 + tid;
        int r  = idx >> 5;
        int k4 = (idx & 31) * 4;
        float4 a = make_float4(0.f, 0.f, 0.f, 0.f);
        int gr = row0 + r;
        if (gr < NN) a = *(const float4*)(A + (size_t)gr * 128 + k4);
        __nv_bfloat16 h0, h1, h2, h3, l0, l1, l2, l3;
        split2(a.x, h0, l0); split2(a.y, h1, l1);
        split2(a.z, h2, l2); split2(a.w, h3, l3);
        uint32_t off = (uint32_t)(r * STRD + k4) * 2;
        uint2 ph = make_uint2(((uint32_t)__bfloat16_as_ushort(h1) << 16) | __bfloat16_as_ushort(h0),
                              ((uint32_t)__bfloat16_as_ushort(h3) << 16) | __bfloat16_as_ushort(h2));
        uint2 pl = make_uint2(((uint32_t)__bfloat16_as_ushort(l1) << 16) | __bfloat16_as_ushort(l0),
                              ((uint32_t)__bfloat16_as_ushort(l3) << 16) | __bfloat16_as_ushort(l2));
        *(uint2*)(smem + SM_AH + off) = ph;
        *(uint2*)(smem + SM_AL + off) = pl;
    }

    const int m0 = wid * 16;
    const int rowsel = lane & 15;
    const int coladd = (lane >> 4) << 3;   // 0 or 8 elements

    for (int which = 0; which < 4; which++) {
        float* O = (which == 0) ? g_q : (which == 1) ? g_k : (which == 2) ? g_v : g_sk;
        const uint32_t bufB = (which & 1) ? (sb + SM_B1) : (sb + SM_B0);

        CP_WAIT0();          // B(which) landed
        __syncthreads();     // visible to all; prior mainloop done before reuse

        if (which < 3) {     // stream in next B while computing
            uint32_t nxt = (which & 1) ? (sb + SM_B0) : (sb + SM_B1);
            issue_b_copy(nxt, layer * 4 + which + 1, tid);
            CP_COMMIT();
        }

        // ---- mma mainloop ----
        float acc[16][4];
        #pragma unroll
        for (int nt = 0; nt < 16; nt++)
            #pragma unroll
            for (int j = 0; j < 4; j++) acc[nt][j] = 0.f;

        #pragma unroll 1
        for (int k0 = 0; k0 < 8; k0++) {
            const int k = k0 * 16;
            uint32_t aoff0 = (uint32_t)((m0 + grp) * STRD + k + qid * 2) * 2;
            uint32_t aoff1 = aoff0 + 8u * STRD * 2u;
            uint32_t ah0 = *(const uint32_t*)(smem + SM_AH + aoff0);
            uint32_t ah1 = *(const uint32_t*)(smem + SM_AH + aoff1);
            uint32_t ah2 = *(const uint32_t*)(smem + SM_AH + aoff0 + 16);
            uint32_t ah3 = *(const uint32_t*)(smem + SM_AH + aoff1 + 16);
            uint32_t al0 = *(const uint32_t*)(smem + SM_AL + aoff0);
            uint32_t al1 = *(const uint32_t*)(smem + SM_AL + aoff1);
            uint32_t al2 = *(const uint32_t*)(smem + SM_AL + aoff0 + 16);
            uint32_t al3 = *(const uint32_t*)(smem + SM_AL + aoff1 + 16);

            uint32_t browH = bufB + (uint32_t)((k + rowsel) * STRD + coladd) * 2;
            uint32_t browL = browH + TILE_B;

            #pragma unroll
            for (int nt2 = 0; nt2 < 8; nt2++) {
                uint32_t bh0, bh1, bh2, bh3, bl0, bl1, bl2, bl3;
                LDMATRIX_X4_T(bh0, bh1, bh2, bh3, browH + nt2 * 32);
                LDMATRIX_X4_T(bl0, bl1, bl2, bl3, browL + nt2 * 32);
                MMA_BF16(acc[2 * nt2],     ah0, ah1, ah2, ah3, bh0, bh1);
                MMA_BF16(acc[2 * nt2],     ah0, ah1, ah2, ah3, bl0, bl1);
                MMA_BF16(acc[2 * nt2],     al0, al1, al2, al3, bh0, bh1);
                MMA_BF16(acc[2 * nt2 + 1], ah0, ah1, ah2, ah3, bh2, bh3);
                MMA_BF16(acc[2 * nt2 + 1], ah0, ah1, ah2, ah3, bl2, bl3);
                MMA_BF16(acc[2 * nt2 + 1], al0, al1, al2, al3, bh2, bh3);
            }
        }

        // ---- epilogue ----
        int r0 = row0 + m0 + grp;
        int r1 = r0 + 8;
        const float* bw = bias_s + which * 128;
        #pragma unroll
        for (int nt = 0; nt < 16; nt++) {
            int c = nt * 8 + qid * 2;
            float b0 = bw[c], b1 = bw[c + 1];
            if (r0 < NN) {
                float2 o = make_float2(acc[nt][0] + b0, acc[nt][1] + b1);
                *(float2*)(O + (size_t)r0 * 128 + c) = o;
            }
            if (r1 < NN) {
                float2 o = make_float2(acc[nt][2] + b0, acc[nt][3] + b1);
                *(float2*)(O + (size_t)r1 * 128 + c) = o;
            }
        }
    }
}

// ---------------- attention: warp per dst node, online softmax, 2 edges/step ----------------
__device__ __forceinline__ float warp_red(float p) {
    p += __shfl_xor_sync(0xffffffffu, p, 16);
    p += __shfl_xor_sync(0xffffffffu, p, 8);
    p += __shfl_xor_sync(0xffffffffu, p, 4);
    p += __shfl_xor_sync(0xffffffffu, p, 2);
    p += __shfl_xor_sync(0xffffffffu, p, 1);
    return p;
}

__global__ __launch_bounds__(256) void attn_kernel() {
    int node = (blockIdx.x * blockDim.x + threadIdx.x) >> 5;
    if (node >= NN) return;
    int lane = threadIdx.x & 31;
    const int base = node * 128 + lane * 4;
    const int lo4  = lane * 4;

    float4 q4 = *(const float4*)(&g_q[base]);
    int beg = g_rowptr[node];
    int end = g_rowptr[node + 1];

    float m = -CUDART_INF_F, den = 0.f;
    float a0 = 0.f, a1 = 0.f, a2 = 0.f, a3 = 0.f;
    const float SCALE = 0.08838834764831845f;

    int i = beg;
    for (; i + 2 <= end; i += 2) {
        int s0 = g_col[i], s1 = g_col[i + 1];
        float4 k0 = *(const float4*)(&g_k[(size_t)s0 * 128 + lo4]);
        float4 k1 = *(const float4*)(&g_k[(size_t)s1 * 128 + lo4]);
        float4 v0 = *(const float4*)(&g_v[(size_t)s0 * 128 + lo4]);
        float4 v1 = *(const float4*)(&g_v[(size_t)s1 * 128 + lo4]);
        float p0 = q4.x * k0.x + q4.y * k0.y + q4.z * k0.z + q4.w * k0.w;
        float p1 = q4.x * k1.x + q4.y * k1.y + q4.z * k1.z + q4.w * k1.w;
        p0 = warp_red(p0);
        p1 = warp_red(p1);
        float sc0 = p0 * SCALE, sc1 = p1 * SCALE;
        float nm = fmaxf(m, fmaxf(sc0, sc1));
        float cm = __expf(m - nm);
        float w0 = __expf(sc0 - nm);
        float w1 = __expf(sc1 - nm);
        den = den * cm + w0 + w1;
        a0 = fmaf(a0, cm, fmaf(w0, v0.x, w1 * v1.x));
        a1 = fmaf(a1, cm, fmaf(w0, v0.y, w1 * v1.y));
        a2 = fmaf(a2, cm, fmaf(w0, v0.z, w1 * v1.z));
        a3 = fmaf(a3, cm, fmaf(w0, v0.w, w1 * v1.w));
        m = nm;
    }
    if (i < end) {
        int s0 = g_col[i];
        float4 k0 = *(const float4*)(&g_k[(size_t)s0 * 128 + lo4]);
        float4 v0 = *(const float4*)(&g_v[(size_t)s0 * 128 + lo4]);
        float p0 = q4.x * k0.x + q4.y * k0.y + q4.z * k0.z + q4.w * k0.w;
        p0 = warp_red(p0);
        float sc0 = p0 * SCALE;
        float nm = fmaxf(m, sc0);
        float cm = __expf(m - nm);
        float w0 = __expf(sc0 - nm);
        den = den * cm + w0;
        a0 = fmaf(a0, cm, w0 * v0.x);
        a1 = fmaf(a1, cm, w0 * v0.y);
        a2 = fmaf(a2, cm, w0 * v0.z);
        a3 = fmaf(a3, cm, w0 * v0.w);
        m = nm;
    }

    float inv = (den > 0.f) ? (1.0f / den) : 0.0f;
    float4 sk4 = *(const float4*)(&g_sk[base]);
    float4 o;
    o.x = fmaxf(fmaf(a0, inv, sk4.x), 0.f);
    o.y = fmaxf(fmaf(a1, inv, sk4.y), 0.f);
    o.z = fmaxf(fmaf(a2, inv, sk4.z), 0.f);
    o.w = fmaxf(fmaf(a3, inv, sk4.w), 0.f);
    *(float4*)(&g_h[base]) = o;
}

// ---------------- pooling ----------------
__global__ void count_kernel(const int* __restrict__ batch) {
    int n = blockIdx.x * blockDim.x + threadIdx.x;
    if (n < NN) atomicAdd(&g_cnt[batch[n]], 1);
}
__global__ __launch_bounds__(128) void pool_kernel(const int* __restrict__ batch) {
    int t = threadIdx.x;
    int n0 = blockIdx.x * 256;
    int nend = min(n0 + 256, NN);
    int gcur = -1;
    float acc = 0.f;
    for (int n = n0; n < nend; n++) {
        int g = batch[n];
        if (g != gcur) {
            if (gcur >= 0) atomicAdd(&g_pool[gcur * 128 + t], acc);
            gcur = g; acc = 0.f;
        }
        acc += g_h[(size_t)n * 128 + t];
    }
    if (gcur >= 0) atomicAdd(&g_pool[gcur * 128 + t], acc);
}

// ---------------- head ----------------
__global__ __launch_bounds__(640) void head_kernel(
    const float* __restrict__ Wfc, const float* __restrict__ bfc, float* __restrict__ out)
{
    __shared__ float logits[GG][NCLS];
    __shared__ float rmax[GG], rlse[GG];
    int t = threadIdx.x;
    int g = t / NCLS, c = t % NCLS;

    float cnt = (float)g_cnt[g];
    if (cnt < 1.f) cnt = 1.f;
    float s = 0.f;
    for (int d = 0; d < 128; d++)
        s += g_pool[g * 128 + d] * Wfc[d * NCLS + c];
    s = s / cnt + bfc[c];
    logits[g][c] = s;
    __syncthreads();

    if (t < GG) {
        float m = -CUDART_INF_F;
        for (int j = 0; j < NCLS; j++) m = fmaxf(m, logits[t][j]);
        float l = 0.f;
        for (int j = 0; j < NCLS; j++) l += expf(logits[t][j] - m);
        rmax[t] = m;
        rlse[t] = logf(l);
    }
    __syncthreads();
    out[g * NCLS + c] = logits[g][c] - rmax[g] - rlse[g];
}

// ---------------- launch ----------------
extern "C" void kernel_launch(void* const* d_in, const int* in_sizes, int n_in,
                              void* d_out, int out_size)
{
    const float* x   = (const float*)d_in[0];
    const int* eidx  = (const int*)d_in[1];
    const int* batch = (const int*)d_in[2];
    const float* Wq  = (const float*)d_in[3];
    const float* bq  = (const float*)d_in[4];
    const float* Wk  = (const float*)d_in[5];
    const float* bk  = (const float*)d_in[6];
    const float* Wv  = (const float*)d_in[7];
    const float* bv  = (const float*)d_in[8];
    const float* Ws  = (const float*)d_in[9];
    const float* bs  = (const float*)d_in[10];
    const float* Wfc = (const float*)d_in[11];
    const float* bfc = (const float*)d_in[12];
    float* out = (float*)d_out;

    const int* src = eidx;        // row 0
    const int* dst = eidx + EE;   // row 1

    static cudaStream_t s2 = nullptr;
    static cudaEvent_t evFork = nullptr, evJoin = nullptr;
    static bool attrSet = false;
    if (!s2) {
        cudaStreamCreateWithFlags(&s2, cudaStreamNonBlocking);
        cudaEventCreateWithFlags(&evFork, cudaEventDisableTiming);
        cudaEventCreateWithFlags(&evJoin, cudaEventDisableTiming);
    }
    if (!attrSet) {
        cudaFuncSetAttribute(gemm_mma_kernel,
                             cudaFuncAttributeMaxDynamicSharedMemorySize, SM_TOT);
        attrSet = true;
    }

    const int scanBlocks = (NN + 511) / 512;   // 98
    const int gemmBlocks     = (NN + 127) / 128;        // 391
    const int nodeWarpBlocks = (NN * 32 + 255) / 256;   // 6250
    const int nodeBlocks     = (NN + 255) / 256;

    cudaEventRecord(evFork, 0);
    cudaStreamWaitEvent(s2, evFork, 0);

    // submission order steers ncu (-s 5): launch #5 = gemm layer 0
    prep_weights_kernel<<<8, 256>>>(Wq, Wk, Wv, Ws);                 // 0
    init_kernel<<<(NN + 255) / 256, 256, 0, s2>>>();                 // 1
    hist_kernel<<<(EE + 255) / 256, 256, 0, s2>>>(dst);              // 2
    scanA_kernel<<<scanBlocks, 512, 0, s2>>>();                      // 3
    scanC_kernel<<<scanBlocks, 512, 0, s2>>>(scanBlocks);            // 4
    gemm_mma_kernel<<<gemmBlocks, 256, SM_TOT>>>(x, 0, 0,            // 5  <- profiled
                                                 bq, bk, bv, bs);
    scatter_kernel<<<(EE + 255) / 256, 256, 0, s2>>>(src, dst);      // 6
    count_kernel<<<nodeBlocks, 256, 0, s2>>>(batch);                 // 7
    cudaEventRecord(evJoin, s2);

    cudaStreamWaitEvent(0, evJoin, 0);
    attn_kernel<<<nodeWarpBlocks, 256>>>();                          // 8

    gemm_mma_kernel<<<gemmBlocks, 256, SM_TOT>>>(nullptr, 1, 1,      // 9
        bq + 128, bk + 128, bv + 128, bs + 128);
    attn_kernel<<<nodeWarpBlocks, 256>>>();                          // 10

    pool_kernel<<<nodeBlocks, 128>>>(batch);                         // 11
    head_kernel<<<1, 640>>>(Wfc, bfc, out);                          // 12
}

// round 15
// speedup vs baseline: 1.4895x; 1.0042x over previous
#include <cuda_runtime.h>
#include <cuda_bf16.h>
#include <math_constants.h>
#include <cstdint>

// Problem constants
#define NN   50000
#define EE   600000
#define DD   128
#define GG   64
#define NCLS 10

static constexpr int STRD   = 136;                  // bf16 elements per row
static constexpr int MATEL  = 128 * STRD;           // 17408 bf16 per matrix image

// ---------------- device scratch ----------------
__device__ float g_h   [NN * DD];
__device__ float g_q   [NN * DD];
__device__ float g_sk  [NN * DD];
__device__ __align__(16) __nv_bfloat16 g_kb[NN * DD];   // k in bf16 (attention-only)
__device__ __align__(16) __nv_bfloat16 g_vb[NN * DD];   // v in bf16

__device__ __align__(16) __nv_bfloat16 g_wbh[8 * MATEL];  // weight hi images
__device__ __align__(16) __nv_bfloat16 g_wbl[8 * MATEL];  // weight lo images

__device__ int   g_deg [NN];
__device__ int   g_cur [NN];
__device__ int   g_rowptr[NN + 1];
__device__ int   g_col [EE];
__device__ int   g_aux [128];

__device__ float g_pool[GG * DD];
__device__ int   g_cnt [GG];

// ---------------- init ----------------
__global__ void init_kernel() {
    int i = blockIdx.x * blockDim.x + threadIdx.x;
    if (i < NN) { g_deg[i] = 0; g_cur[i] = 0; }
    if (i < GG * DD) g_pool[i] = 0.0f;
    if (i < GG) g_cnt[i] = 0;
}

// ---------------- CSR build ----------------
__global__ void hist_kernel(const int* __restrict__ dst) {
    int e = blockIdx.x * blockDim.x + threadIdx.x;
    if (e < EE) atomicAdd(&g_deg[dst[e]], 1);
}
__global__ void scanA_kernel() {
    __shared__ int s[512];
    int t = threadIdx.x;
    int idx = blockIdx.x * 512 + t;
    int val = (idx < NN) ? g_deg[idx] : 0;
    s[t] = val;
    __syncthreads();
    for (int off = 1; off < 512; off <<= 1) {
        int x = (t >= off) ? s[t - off] : 0;
        __syncthreads();
        s[t] += x;
        __syncthreads();
    }
    if (idx < NN) g_rowptr[idx] = s[t];
    if (t == 511) g_aux[blockIdx.x] = s[511];
}
__global__ void scanC_kernel(int nblocks) {
    __shared__ int aux[128];
    int t = threadIdx.x;
    if (t < 128) aux[t] = (t < nblocks) ? g_aux[t] : 0;
    __syncthreads();
    for (int off = 1; off < 128; off <<= 1) {
        int x = 0;
        if (t < 128 && t >= off) x = aux[t - off];
        __syncthreads();
        if (t < 128) aux[t] += x;
        __syncthreads();
    }
    int blockOff = (blockIdx.x == 0) ? 0 : aux[blockIdx.x - 1];
    int idx = blockIdx.x * 512 + t;
    if (idx < NN) g_rowptr[idx] = g_rowptr[idx] - g_deg[idx] + blockOff;
    if (idx == 0) g_rowptr[NN] = EE;
}
__global__ void scatter_kernel(const int* __restrict__ src, const int* __restrict__ dst) {
    int e = blockIdx.x * blockDim.x + threadIdx.x;
    if (e < EE) {
        int d = dst[e];
        int pos = g_rowptr[d] + atomicAdd(&g_cur[d], 1);
        g_col[pos] = src[e];
    }
}

// ---------------- weight prep ----------------
__device__ __forceinline__ void split2(float x, __nv_bfloat16& h, __nv_bfloat16& l) {
    h = __float2bfloat16_rn(x);
    l = __float2bfloat16_rn(x - __bfloat162float(h));
}
__global__ __launch_bounds__(256) void prep_weights_kernel(
    const float* __restrict__ Wq, const float* __restrict__ Wk,
    const float* __restrict__ Wv, const float* __restrict__ Ws)
{
    int layer = blockIdx.x >> 2;
    int which = blockIdx.x & 3;
    const float* W = (which == 0) ? Wq : (which == 1) ? Wk : (which == 2) ? Wv : Ws;
    W += layer * 128 * 128;
    size_t outBase = (size_t)blockIdx.x * MATEL;
    for (int idx = threadIdx.x; idx < 128 * 128; idx += 256) {
        int k = idx >> 7, n = idx & 127;
        __nv_bfloat16 h, l;
        split2(W[idx], h, l);
        size_t o = outBase + (size_t)k * STRD + n;
        g_wbh[o] = h;
        g_wbl[o] = l;
    }
}

// ---------------- HMMA GEMM ----------------
static constexpr int TILE_B = MATEL * 2;            // 34816 bytes
static constexpr int SM_AH   = 0;
static constexpr int SM_AL   = SM_AH + TILE_B;
static constexpr int SM_B0   = 69632;
static constexpr int SM_B1   = 139264;
static constexpr int SM_BIAS = 208896;
static constexpr int SM_TOT  = 210944;

#define MMA_BF16(d, a0, a1, a2, a3, b0, b1) \
    asm volatile( \
        "mma.sync.aligned.m16n8k16.row.col.f32.bf16.bf16.f32 " \
        "{%0,%1,%2,%3}, {%4,%5,%6,%7}, {%8,%9}, {%0,%1,%2,%3};" \
        : "+f"((d)[0]), "+f"((d)[1]), "+f"((d)[2]), "+f"((d)[3]) \
        : "r"(a0), "r"(a1), "r"(a2), "r"(a3), "r"(b0), "r"(b1))

#define LDMATRIX_X4_T(r0, r1, r2, r3, addr) \
    asm volatile("ldmatrix.sync.aligned.m8n8.x4.trans.shared.b16 {%0,%1,%2,%3}, [%4];" \
                 : "=r"(r0), "=r"(r1), "=r"(r2), "=r"(r3) : "r"(addr))

#define CP_ASYNC16(dst, src) \
    asm volatile("cp.async.cg.shared.global [%0], [%1], 16;" :: "r"(dst), "l"(src))
#define CP_COMMIT()  asm volatile("cp.async.commit_group;" ::: "memory")
#define CP_WAIT0()   asm volatile("cp.async.wait_group 0;" ::: "memory")

__device__ __forceinline__ uint32_t smem_u32(const void* p) {
    uint32_t a;
    asm("{ .reg .u64 t; cvta.to.shared.u64 t, %1; cvt.u32.u64 %0, t; }" : "=r"(a) : "l"(p));
    return a;
}

__device__ __forceinline__ void issue_b_copy(uint32_t dstBase, int mat, int tid) {
    const char* sH = (const char*)(g_wbh + (size_t)mat * MATEL);
    const char* sL = (const char*)(g_wbl + (size_t)mat * MATEL);
    #pragma unroll
    for (int it = 0; it < 17; it++) {
        int f = it * 256 + tid;
        const char* src = (f < 2176) ? (sH + (size_t)f * 16)
                                     : (sL + (size_t)(f - 2176) * 16);
        CP_ASYNC16(dstBase + f * 16, src);
    }
}

__global__ __launch_bounds__(256) void gemm_mma_kernel(
    const float* __restrict__ Ain, int useGh, int layer,
    const float* __restrict__ bq, const float* __restrict__ bk,
    const float* __restrict__ bv, const float* __restrict__ bs)
{
    extern __shared__ char smem[];
    const float* A = useGh ? (const float*)g_h : Ain;
    const uint32_t sb = smem_u32(smem);
    const int tid  = threadIdx.x;
    const int wid  = tid >> 5;
    const int lane = tid & 31;
    const int grp  = lane >> 2;
    const int qid  = lane & 3;
    const int row0 = blockIdx.x * 128;
    float* bias_s = (float*)(smem + SM_BIAS);

    issue_b_copy(sb + SM_B0, layer * 4 + 0, tid);
    CP_COMMIT();

    if (tid < 128) {
        bias_s[tid]       = bq[tid];
        bias_s[tid + 128] = bk[tid];
        bias_s[tid + 256] = bv[tid];
        bias_s[tid + 384] = bs[tid];
    }

    // ---- A tile: fp32 -> bf16 hi/lo ----
    for (int it = 0; it < 16; it++) {
        int idx = it * 256 + tid;
        int r  = idx >> 5;
        int k4 = (idx & 31) * 4;
        float4 a = make_float4(0.f, 0.f, 0.f, 0.f);
        int gr = row0 + r;
        if (gr < NN) a = *(const float4*)(A + (size_t)gr * 128 + k4);
        __nv_bfloat16 h0, h1, h2, h3, l0, l1, l2, l3;
        split2(a.x, h0, l0); split2(a.y, h1, l1);
        split2(a.z, h2, l2); split2(a.w, h3, l3);
        uint32_t off = (uint32_t)(r * STRD + k4) * 2;
        uint2 ph = make_uint2(((uint32_t)__bfloat16_as_ushort(h1) << 16) | __bfloat16_as_ushort(h0),
                              ((uint32_t)__bfloat16_as_ushort(h3) << 16) | __bfloat16_as_ushort(h2));
        uint2 pl = make_uint2(((uint32_t)__bfloat16_as_ushort(l1) << 16) | __bfloat16_as_ushort(l0),
                              ((uint32_t)__bfloat16_as_ushort(l3) << 16) | __bfloat16_as_ushort(l2));
        *(uint2*)(smem + SM_AH + off) = ph;
        *(uint2*)(smem + SM_AL + off) = pl;
    }

    const int m0 = wid * 16;
    const int rowsel = lane & 15;
    const int coladd = (lane >> 4) << 3;

    for (int which = 0; which < 4; which++) {
        const uint32_t bufB = (which & 1) ? (sb + SM_B1) : (sb + SM_B0);

        CP_WAIT0();
        __syncthreads();

        if (which < 3) {
            uint32_t nxt = (which & 1) ? (sb + SM_B0) : (sb + SM_B1);
            issue_b_copy(nxt, layer * 4 + which + 1, tid);
            CP_COMMIT();
        }

        float acc[16][4];
        #pragma unroll
        for (int nt = 0; nt < 16; nt++)
            #pragma unroll
            for (int j = 0; j < 4; j++) acc[nt][j] = 0.f;

        #pragma unroll 1
        for (int k0 = 0; k0 < 8; k0++) {
            const int k = k0 * 16;
            uint32_t aoff0 = (uint32_t)((m0 + grp) * STRD + k + qid * 2) * 2;
            uint32_t aoff1 = aoff0 + 8u * STRD * 2u;
            uint32_t ah0 = *(const uint32_t*)(smem + SM_AH + aoff0);
            uint32_t ah1 = *(const uint32_t*)(smem + SM_AH + aoff1);
            uint32_t ah2 = *(const uint32_t*)(smem + SM_AH + aoff0 + 16);
            uint32_t ah3 = *(const uint32_t*)(smem + SM_AH + aoff1 + 16);
            uint32_t al0 = *(const uint32_t*)(smem + SM_AL + aoff0);
            uint32_t al1 = *(const uint32_t*)(smem + SM_AL + aoff1);
            uint32_t al2 = *(const uint32_t*)(smem + SM_AL + aoff0 + 16);
            uint32_t al3 = *(const uint32_t*)(smem + SM_AL + aoff1 + 16);

            uint32_t browH = bufB + (uint32_t)((k + rowsel) * STRD + coladd) * 2;
            uint32_t browL = browH + TILE_B;

            #pragma unroll
            for (int nt2 = 0; nt2 < 8; nt2++) {
                uint32_t bh0, bh1, bh2, bh3, bl0, bl1, bl2, bl3;
                LDMATRIX_X4_T(bh0, bh1, bh2, bh3, browH + nt2 * 32);
                LDMATRIX_X4_T(bl0, bl1, bl2, bl3, browL + nt2 * 32);
                MMA_BF16(acc[2 * nt2],     ah0, ah1, ah2, ah3, bh0, bh1);
                MMA_BF16(acc[2 * nt2],     ah0, ah1, ah2, ah3, bl0, bl1);
                MMA_BF16(acc[2 * nt2],     al0, al1, al2, al3, bh0, bh1);
                MMA_BF16(acc[2 * nt2 + 1], ah0, ah1, ah2, ah3, bh2, bh3);
                MMA_BF16(acc[2 * nt2 + 1], ah0, ah1, ah2, ah3, bl2, bl3);
                MMA_BF16(acc[2 * nt2 + 1], al0, al1, al2, al3, bh2, bh3);
            }
        }

        // ---- epilogue: q/skip -> fp32, k/v -> bf16 ----
        int r0 = row0 + m0 + grp;
        int r1 = r0 + 8;
        const float* bw = bias_s + which * 128;
        if (which == 1 || which == 2) {
            uint32_t* Ob = (uint32_t*)((which == 1) ? g_kb : g_vb);
            #pragma unroll
            for (int nt = 0; nt < 16; nt++) {
                int c = nt * 8 + qid * 2;
                float b0 = bw[c], b1 = bw[c + 1];
                if (r0 < NN) {
                    __nv_bfloat162 p = __floats2bfloat162_rn(acc[nt][0] + b0, acc[nt][1] + b1);
                    Ob[((size_t)r0 * 128 + c) >> 1] = *(uint32_t*)&p;
                }
                if (r1 < NN) {
                    __nv_bfloat162 p = __floats2bfloat162_rn(acc[nt][2] + b0, acc[nt][3] + b1);
                    Ob[((size_t)r1 * 128 + c) >> 1] = *(uint32_t*)&p;
                }
            }
        } else {
            float* O = (which == 0) ? g_q : g_sk;
            #pragma unroll
            for (int nt = 0; nt < 16; nt++) {
                int c = nt * 8 + qid * 2;
                float b0 = bw[c], b1 = bw[c + 1];
                if (r0 < NN) {
                    float2 o = make_float2(acc[nt][0] + b0, acc[nt][1] + b1);
                    *(float2*)(O + (size_t)r0 * 128 + c) = o;
                }
                if (r1 < NN) {
                    float2 o = make_float2(acc[nt][2] + b0, acc[nt][3] + b1);
                    *(float2*)(O + (size_t)r1 * 128 + c) = o;
                }
            }
        }
    }
}

// ---------------- attention: warp per dst node, bf16 k/v gather ----------------
__device__ __forceinline__ float warp_red(float p) {
    p += __shfl_xor_sync(0xffffffffu, p, 16);
    p += __shfl_xor_sync(0xffffffffu, p, 8);
    p += __shfl_xor_sync(0xffffffffu, p, 4);
    p += __shfl_xor_sync(0xffffffffu, p, 2);
    p += __shfl_xor_sync(0xffffffffu, p, 1);
    return p;
}
__device__ __forceinline__ float4 ld_bf16x4(const __nv_bfloat16* p) {
    uint2 u = *(const uint2*)p;
    __nv_bfloat162 b0 = *(__nv_bfloat162*)&u.x;
    __nv_bfloat162 b1 = *(__nv_bfloat162*)&u.y;
    float2 f0 = __bfloat1622float2(b0);
    float2 f1 = __bfloat1622float2(b1);
    return make_float4(f0.x, f0.y, f1.x, f1.y);
}

__global__ __launch_bounds__(256) void attn_kernel() {
    int node = (blockIdx.x * blockDim.x + threadIdx.x) >> 5;
    if (node >= NN) return;
    int lane = threadIdx.x & 31;
    const int base = node * 128 + lane * 4;
    const int lo4  = lane * 4;

    float4 q4 = *(const float4*)(&g_q[base]);
    int beg = g_rowptr[node];
    int end = g_rowptr[node + 1];

    float m = -CUDART_INF_F, den = 0.f;
    float a0 = 0.f, a1 = 0.f, a2 = 0.f, a3 = 0.f;
    const float SCALE = 0.08838834764831845f;

    int i = beg;
    for (; i + 2 <= end; i += 2) {
        int s0 = g_col[i], s1 = g_col[i + 1];
        float4 k0 = ld_bf16x4(g_kb + (size_t)s0 * 128 + lo4);
        float4 k1 = ld_bf16x4(g_kb + (size_t)s1 * 128 + lo4);
        float4 v0 = ld_bf16x4(g_vb + (size_t)s0 * 128 + lo4);
        float4 v1 = ld_bf16x4(g_vb + (size_t)s1 * 128 + lo4);
        float p0 = q4.x * k0.x + q4.y * k0.y + q4.z * k0.z + q4.w * k0.w;
        float p1 = q4.x * k1.x + q4.y * k1.y + q4.z * k1.z + q4.w * k1.w;
        p0 = warp_red(p0);
        p1 = warp_red(p1);
        float sc0 = p0 * SCALE, sc1 = p1 * SCALE;
        float nm = fmaxf(m, fmaxf(sc0, sc1));
        float cm = __expf(m - nm);
        float w0 = __expf(sc0 - nm);
        float w1 = __expf(sc1 - nm);
        den = den * cm + w0 + w1;
        a0 = fmaf(a0, cm, fmaf(w0, v0.x, w1 * v1.x));
        a1 = fmaf(a1, cm, fmaf(w0, v0.y, w1 * v1.y));
        a2 = fmaf(a2, cm, fmaf(w0, v0.z, w1 * v1.z));
        a3 = fmaf(a3, cm, fmaf(w0, v0.w, w1 * v1.w));
        m = nm;
    }
    if (i < end) {
        int s0 = g_col[i];
        float4 k0 = ld_bf16x4(g_kb + (size_t)s0 * 128 + lo4);
        float4 v0 = ld_bf16x4(g_vb + (size_t)s0 * 128 + lo4);
        float p0 = q4.x * k0.x + q4.y * k0.y + q4.z * k0.z + q4.w * k0.w;
        p0 = warp_red(p0);
        float sc0 = p0 * SCALE;
        float nm = fmaxf(m, sc0);
        float cm = __expf(m - nm);
        float w0 = __expf(sc0 - nm);
        den = den * cm + w0;
        a0 = fmaf(a0, cm, w0 * v0.x);
        a1 = fmaf(a1, cm, w0 * v0.y);
        a2 = fmaf(a2, cm, w0 * v0.z);
        a3 = fmaf(a3, cm, w0 * v0.w);
        m = nm;
    }

    float inv = (den > 0.f) ? (1.0f / den) : 0.0f;
    float4 sk4 = *(const float4*)(&g_sk[base]);
    float4 o;
    o.x = fmaxf(fmaf(a0, inv, sk4.x), 0.f);
    o.y = fmaxf(fmaf(a1, inv, sk4.y), 0.f);
    o.z = fmaxf(fmaf(a2, inv, sk4.z), 0.f);
    o.w = fmaxf(fmaf(a3, inv, sk4.w), 0.f);
    *(float4*)(&g_h[base]) = o;
}

// ---------------- pooling ----------------
__global__ void count_kernel(const int* __restrict__ batch) {
    int n = blockIdx.x * blockDim.x + threadIdx.x;
    if (n < NN) atomicAdd(&g_cnt[batch[n]], 1);
}
__global__ __launch_bounds__(128) void pool_kernel(const int* __restrict__ batch) {
    int t = threadIdx.x;
    int n0 = blockIdx.x * 256;
    int nend = min(n0 + 256, NN);
    int gcur = -1;
    float acc = 0.f;
    for (int n = n0; n < nend; n++) {
        int g = batch[n];
        if (g != gcur) {
            if (gcur >= 0) atomicAdd(&g_pool[gcur * 128 + t], acc);
            gcur = g; acc = 0.f;
        }
        acc += g_h[(size_t)n * 128 + t];
    }
    if (gcur >= 0) atomicAdd(&g_pool[gcur * 128 + t], acc);
}

// ---------------- head ----------------
__global__ __launch_bounds__(640) void head_kernel(
    const float* __restrict__ Wfc, const float* __restrict__ bfc, float* __restrict__ out)
{
    __shared__ float logits[GG][NCLS];
    __shared__ float rmax[GG], rlse[GG];
    int t = threadIdx.x;
    int g = t / NCLS, c = t % NCLS;

    float cnt = (float)g_cnt[g];
    if (cnt < 1.f) cnt = 1.f;
    float s = 0.f;
    for (int d = 0; d < 128; d++)
        s += g_pool[g * 128 + d] * Wfc[d * NCLS + c];
    s = s / cnt + bfc[c];
    logits[g][c] = s;
    __syncthreads();

    if (t < GG) {
        float m = -CUDART_INF_F;
        for (int j = 0; j < NCLS; j++) m = fmaxf(m, logits[t][j]);
        float l = 0.f;
        for (int j = 0; j < NCLS; j++) l += expf(logits[t][j] - m);
        rmax[t] = m;
        rlse[t] = logf(l);
    }
    __syncthreads();
    out[g * NCLS + c] = logits[g][c] - rmax[g] - rlse[g];
}

// ---------------- launch ----------------
extern "C" void kernel_launch(void* const* d_in, const int* in_sizes, int n_in,
                              void* d_out, int out_size)
{
    const float* x   = (const float*)d_in[0];
    const int* eidx  = (const int*)d_in[1];
    const int* batch = (const int*)d_in[2];
    const float* Wq  = (const float*)d_in[3];
    const float* bq  = (const float*)d_in[4];
    const float* Wk  = (const float*)d_in[5];
    const float* bk  = (const float*)d_in[6];
    const float* Wv  = (const float*)d_in[7];
    const float* bv  = (const float*)d_in[8];
    const float* Ws  = (const float*)d_in[9];
    const float* bs  = (const float*)d_in[10];
    const float* Wfc = (const float*)d_in[11];
    const float* bfc = (const float*)d_in[12];
    float* out = (float*)d_out;

    const int* src = eidx;        // row 0
    const int* dst = eidx + EE;   // row 1

    static cudaStream_t s2 = nullptr;
    static cudaEvent_t evFork = nullptr, evJoin = nullptr;
    static bool attrSet = false;
    if (!s2) {
        cudaStreamCreateWithFlags(&s2, cudaStreamNonBlocking);
        cudaEventCreateWithFlags(&evFork, cudaEventDisableTiming);
        cudaEventCreateWithFlags(&evJoin, cudaEventDisableTiming);
    }
    if (!attrSet) {
        cudaFuncSetAttribute(gemm_mma_kernel,
                             cudaFuncAttributeMaxDynamicSharedMemorySize, SM_TOT);
        attrSet = true;
    }

    const int scanBlocks = (NN + 511) / 512;   // 98
    const int gemmBlocks     = (NN + 127) / 128;        // 391
    const int nodeWarpBlocks = (NN * 32 + 255) / 256;   // 6250
    const int nodeBlocks     = (NN + 255) / 256;

    cudaEventRecord(evFork, 0);
    cudaStreamWaitEvent(s2, evFork, 0);

    prep_weights_kernel<<<8, 256>>>(Wq, Wk, Wv, Ws);                 // 0
    init_kernel<<<(NN + 255) / 256, 256, 0, s2>>>();                 // 1
    hist_kernel<<<(EE + 255) / 256, 256, 0, s2>>>(dst);              // 2
    scanA_kernel<<<scanBlocks, 512, 0, s2>>>();                      // 3
    scanC_kernel<<<scanBlocks, 512, 0, s2>>>(scanBlocks);            // 4
    gemm_mma_kernel<<<gemmBlocks, 256, SM_TOT>>>(x, 0, 0,            // 5 <- profiled
                                                 bq, bk, bv, bs);
    scatter_kernel<<<(EE + 255) / 256, 256, 0, s2>>>(src, dst);      // 6
    count_kernel<<<nodeBlocks, 256, 0, s2>>>(batch);                 // 7
    cudaEventRecord(evJoin, s2);

    cudaStreamWaitEvent(0, evJoin, 0);
    attn_kernel<<<nodeWarpBlocks, 256>>>();                          // 8

    gemm_mma_kernel<<<gemmBlocks, 256, SM_TOT>>>(nullptr, 1, 1,      // 9
        bq + 128, bk + 128, bv + 128, bs + 128);
    attn_kernel<<<nodeWarpBlocks, 256>>>();                          // 10

    pool_kernel<<<nodeBlocks, 128>>>(batch);                         // 11
    head_kernel<<<1, 640>>>(Wfc, bfc, out);                          // 12
}